// round 3
// baseline (speedup 1.0000x reference)
#include <cuda_runtime.h>
#include <math.h>

#define NN 100000
#define NE 1600000
#define NG 512
#define NF 64
#define H1 128
#define H2 64

// ---------------- device scratch ----------------
__device__ float g_h1[NN * H1];      // after nfc (and conv1 input)
__device__ float g_s1[NN * H1];      // conv1 output
__device__ float g_h2[NN * H2];      // conv2 output (normalized)
__device__ float g_e[NN];            // attention logits / exp
__device__ int   g_cnt[NN];
__device__ int   g_off[NN + 1];
__device__ int   g_cur[NN];
__device__ int   g_csr[NE];          // src node per incoming-edge slot (keyed by dst)
__device__ int   g_gs[NG + 1];       // graph start offsets (batch is sorted)
__device__ float g_qstar[NG * 2 * H2];
__device__ float g_st[4 * NG * H2];  // h0 | c0 | h1 | c1

__device__ __forceinline__ float gelu_f(float x) {
    return 0.5f * x * (1.0f + erff(x * 0.70710678118654752f));
}
__device__ __forceinline__ float sigmoid_f(float x) {
    return 1.0f / (1.0f + expf(-x));
}

// ---------------- init ----------------
__global__ void __launch_bounds__(256) k_zero() {
    int i = blockIdx.x * blockDim.x + threadIdx.x;
    int T = gridDim.x * blockDim.x;
    for (int j = i; j < NN; j += T) { g_cnt[j] = 0; g_cur[j] = 0; }
    for (int j = i; j < 4 * NG * H2; j += T) g_st[j] = 0.0f;
    for (int j = i; j < NG * 2 * H2; j += T) g_qstar[j] = 0.0f;
}

// ---------------- CSR build ----------------
__global__ void __launch_bounds__(256) k_count(const int* __restrict__ ei) {
    int e = blockIdx.x * blockDim.x + threadIdx.x;
    if (e < NE) atomicAdd(&g_cnt[ei[NE + e]], 1);
}

__global__ void __launch_bounds__(256) k_scan() {   // single block, 256 threads
    __shared__ int sums[256];
    const int CH = (NN + 255) / 256;   // 391
    int tid = threadIdx.x;
    int base = tid * CH;
    int s = 0;
    for (int i = 0; i < CH; i++) {
        int idx = base + i;
        if (idx < NN) s += g_cnt[idx];
    }
    sums[tid] = s;
    __syncthreads();
    for (int off = 1; off < 256; off <<= 1) {
        int v = (tid >= off) ? sums[tid - off] : 0;
        __syncthreads();
        sums[tid] += v;
        __syncthreads();
    }
    int run = sums[tid] - s;   // exclusive prefix of this chunk
    for (int i = 0; i < CH; i++) {
        int idx = base + i;
        if (idx < NN) { g_off[idx] = run; run += g_cnt[idx]; }
    }
    if (tid == 255) g_off[NN] = sums[255];
}

__global__ void __launch_bounds__(256) k_scatter(const int* __restrict__ ei) {
    int e = blockIdx.x * blockDim.x + threadIdx.x;
    if (e < NE) {
        int s = ei[e];
        int d = ei[NE + e];
        int pos = atomicAdd(&g_cur[d], 1);
        g_csr[g_off[d] + pos] = s;
    }
}

__global__ void __launch_bounds__(256) k_gstart(const int* __restrict__ batch) {
    int n = blockIdx.x * blockDim.x + threadIdx.x;
    if (n < NN) {
        int b = batch[n];
        int bp = (n == 0) ? -1 : batch[n - 1];
        for (int g = bp + 1; g <= b; g++) g_gs[g] = n;
        if (n == NN - 1)
            for (int g = b + 1; g <= NG; g++) g_gs[g] = NN;
    }
}

// ---------------- nfc: h = gelu(x @ W.T + b), [NN,64] -> [NN,128] ----------------
__global__ void __launch_bounds__(256) k_nfc(const float* __restrict__ x,
                      const float* __restrict__ W,
                      const float* __restrict__ b) {
    extern __shared__ float sm[];
    float* wt = sm;               // [64][128] transposed
    float* xs = sm + NF * H1;     // [8][64]
    int tid = threadIdx.x;
    for (int i = tid; i < H1 * NF; i += blockDim.x) {
        int o = i / NF, k = i % NF;
        wt[k * H1 + o] = W[i];
    }
    __syncthreads();
    int warp = tid >> 5, lane = tid & 31;
    int n = blockIdx.x * 8 + warp;
    if (n >= NN) return;
    float2 xv = *(const float2*)&x[n * NF + lane * 2];
    xs[warp * NF + lane * 2]     = xv.x;
    xs[warp * NF + lane * 2 + 1] = xv.y;
    __syncwarp();
    float4 acc = *(const float4*)&b[lane * 4];
    const float* xr = &xs[warp * NF];
#pragma unroll 16
    for (int k = 0; k < NF; k++) {
        float xk = xr[k];
        float4 w = *(const float4*)&wt[k * H1 + lane * 4];
        acc.x = fmaf(xk, w.x, acc.x);
        acc.y = fmaf(xk, w.y, acc.y);
        acc.z = fmaf(xk, w.z, acc.z);
        acc.w = fmaf(xk, w.w, acc.w);
    }
    acc.x = gelu_f(acc.x); acc.y = gelu_f(acc.y);
    acc.z = gelu_f(acc.z); acc.w = gelu_f(acc.w);
    *(float4*)&g_h1[n * H1 + lane * 4] = acc;
}

// ---------------- conv1: gather+self, GEMM 128x128, gelu -> g_s1 ----------------
__global__ void __launch_bounds__(256) k_conv1(const float* __restrict__ W,
                        const float* __restrict__ b) {
    extern __shared__ float sm[];
    float* wt = sm;                // [128][128] transposed
    float* ss = sm + H1 * H1;      // [8][128]
    int tid = threadIdx.x;
    for (int i = tid; i < H1 * H1; i += blockDim.x) {
        int o = i / H1, k = i % H1;
        wt[k * H1 + o] = W[i];
    }
    __syncthreads();
    int warp = tid >> 5, lane = tid & 31;
    int n = blockIdx.x * 8 + warp;
    if (n >= NN) return;
    float4 a = *(const float4*)&g_h1[n * H1 + lane * 4];   // self
    int e0 = g_off[n], e1 = g_off[n + 1];
    int j = e0;
    for (; j + 1 < e1; j += 2) {
        int s0 = g_csr[j], s1 = g_csr[j + 1];
        float4 v0 = *(const float4*)&g_h1[s0 * H1 + lane * 4];
        float4 v1 = *(const float4*)&g_h1[s1 * H1 + lane * 4];
        a.x += v0.x + v1.x; a.y += v0.y + v1.y;
        a.z += v0.z + v1.z; a.w += v0.w + v1.w;
    }
    if (j < e1) {
        int s0 = g_csr[j];
        float4 v0 = *(const float4*)&g_h1[s0 * H1 + lane * 4];
        a.x += v0.x; a.y += v0.y; a.z += v0.z; a.w += v0.w;
    }
    *(float4*)&ss[warp * H1 + lane * 4] = a;
    __syncwarp();
    float4 acc = *(const float4*)&b[lane * 4];
    const float* sr = &ss[warp * H1];
#pragma unroll 16
    for (int k = 0; k < H1; k++) {
        float sk = sr[k];
        float4 w = *(const float4*)&wt[k * H1 + lane * 4];
        acc.x = fmaf(sk, w.x, acc.x);
        acc.y = fmaf(sk, w.y, acc.y);
        acc.z = fmaf(sk, w.z, acc.z);
        acc.w = fmaf(sk, w.w, acc.w);
    }
    acc.x = gelu_f(acc.x); acc.y = gelu_f(acc.y);
    acc.z = gelu_f(acc.z); acc.w = gelu_f(acc.w);
    *(float4*)&g_s1[n * H1 + lane * 4] = acc;
}

// ---------------- conv2: gather+self, GEMM 128->64, gelu, L2-normalize ----------------
__global__ void __launch_bounds__(256) k_conv2(const float* __restrict__ W,
                        const float* __restrict__ b,
                        float* __restrict__ out_h) {
    extern __shared__ float sm[];
    float* wt = sm;                // [128][64] transposed
    float* ss = sm + H1 * H2;      // [8][128]
    int tid = threadIdx.x;
    for (int i = tid; i < H2 * H1; i += blockDim.x) {
        int o = i / H1, k = i % H1;
        wt[k * H2 + o] = W[i];
    }
    __syncthreads();
    int warp = tid >> 5, lane = tid & 31;
    int n = blockIdx.x * 8 + warp;
    if (n >= NN) return;
    float4 a = *(const float4*)&g_s1[n * H1 + lane * 4];
    int e0 = g_off[n], e1 = g_off[n + 1];
    int j = e0;
    for (; j + 1 < e1; j += 2) {
        int s0 = g_csr[j], s1 = g_csr[j + 1];
        float4 v0 = *(const float4*)&g_s1[s0 * H1 + lane * 4];
        float4 v1 = *(const float4*)&g_s1[s1 * H1 + lane * 4];
        a.x += v0.x + v1.x; a.y += v0.y + v1.y;
        a.z += v0.z + v1.z; a.w += v0.w + v1.w;
    }
    if (j < e1) {
        int s0 = g_csr[j];
        float4 v0 = *(const float4*)&g_s1[s0 * H1 + lane * 4];
        a.x += v0.x; a.y += v0.y; a.z += v0.z; a.w += v0.w;
    }
    *(float4*)&ss[warp * H1 + lane * 4] = a;
    __syncwarp();
    float2 acc = *(const float2*)&b[lane * 2];
    const float* sr = &ss[warp * H1];
#pragma unroll 16
    for (int k = 0; k < H1; k++) {
        float sk = sr[k];
        float2 w = *(const float2*)&wt[k * H2 + lane * 2];
        acc.x = fmaf(sk, w.x, acc.x);
        acc.y = fmaf(sk, w.y, acc.y);
    }
    acc.x = gelu_f(acc.x);
    acc.y = gelu_f(acc.y);
    float ssq = acc.x * acc.x + acc.y * acc.y;
#pragma unroll
    for (int off = 16; off; off >>= 1) ssq += __shfl_xor_sync(0xFFFFFFFFu, ssq, off);
    float inv = 1.0f / fmaxf(sqrtf(ssq), 1e-12f);
    acc.x *= inv; acc.y *= inv;
    *(float2*)&g_h2[n * H2 + lane * 2] = acc;
    if (out_h) *(float2*)&out_h[n * H2 + lane * 2] = acc;
}

// ---------------- 2-layer LSTM cell step: 8 graphs per block ----------------
__global__ void __launch_bounds__(256) k_lstm(const float* __restrict__ Wih0, const float* __restrict__ Whh0,
                       const float* __restrict__ bih0, const float* __restrict__ bhh0,
                       const float* __restrict__ Wih1, const float* __restrict__ Whh1,
                       const float* __restrict__ bih1, const float* __restrict__ bhh1) {
    __shared__ float xsh[2 * H2], h0s[H2], h1s[H2], gb[4 * H2], h0n[H2];
    int tid = threadIdx.x;   // 256
    for (int gi = 0; gi < 8; gi++) {
        int g = blockIdx.x * 8 + gi;
        if (tid < 2 * H2) xsh[tid] = g_qstar[g * 2 * H2 + tid];
        if (tid < H2) {
            h0s[tid] = g_st[g * H2 + tid];
            h1s[tid] = g_st[2 * NG * H2 + g * H2 + tid];
        }
        __syncthreads();
        // layer 0 gates
        float gate = bih0[tid] + bhh0[tid];
        const float* wi = &Wih0[tid * (2 * H2)];
#pragma unroll 16
        for (int k = 0; k < 2 * H2; k++) gate = fmaf(wi[k], xsh[k], gate);
        const float* wh = &Whh0[tid * H2];
#pragma unroll 16
        for (int k = 0; k < H2; k++) gate = fmaf(wh[k], h0s[k], gate);
        gb[tid] = gate;
        __syncthreads();
        if (tid < H2) {
            float i = sigmoid_f(gb[tid]);
            float f = sigmoid_f(gb[H2 + tid]);
            float gg = tanhf(gb[2 * H2 + tid]);
            float o = sigmoid_f(gb[3 * H2 + tid]);
            float c = f * g_st[NG * H2 + g * H2 + tid] + i * gg;
            g_st[NG * H2 + g * H2 + tid] = c;
            float h = o * tanhf(c);
            g_st[g * H2 + tid] = h;
            h0n[tid] = h;
        }
        __syncthreads();
        // layer 1 gates
        float gate2 = bih1[tid] + bhh1[tid];
        const float* wi1 = &Wih1[tid * H2];
#pragma unroll 16
        for (int k = 0; k < H2; k++) gate2 = fmaf(wi1[k], h0n[k], gate2);
        const float* wh1 = &Whh1[tid * H2];
#pragma unroll 16
        for (int k = 0; k < H2; k++) gate2 = fmaf(wh1[k], h1s[k], gate2);
        gb[tid] = gate2;
        __syncthreads();
        if (tid < H2) {
            float i = sigmoid_f(gb[tid]);
            float f = sigmoid_f(gb[H2 + tid]);
            float gg = tanhf(gb[2 * H2 + tid]);
            float o = sigmoid_f(gb[3 * H2 + tid]);
            float c = f * g_st[3 * NG * H2 + g * H2 + tid] + i * gg;
            g_st[3 * NG * H2 + g * H2 + tid] = c;
            float h = o * tanhf(c);
            g_st[2 * NG * H2 + g * H2 + tid] = h;
            g_qstar[g * 2 * H2 + tid] = h;   // q part of q_star
        }
        __syncthreads();
    }
}

// ---------------- attention (one block per graph, batch sorted) ----------------
__global__ void __launch_bounds__(256) k_attn() {
    int g = blockIdx.x;
    __shared__ float q[H2], red[8], rbuf[8 * H2];
    __shared__ float smax, ssum_s;
    int tid = threadIdx.x;   // 256
    int warp = tid >> 5, lane = tid & 31;
    int gs = g_gs[g], ge = g_gs[g + 1];
    if (tid < H2) q[tid] = g_qstar[g * 2 * H2 + tid];
    __syncthreads();
    // phase 1: logits + max (warp per node)
    float wmax = -3.4e38f;
    for (int n = gs + warp; n < ge; n += 8) {
        float2 hv = *(const float2*)&g_h2[n * H2 + lane * 2];
        float e = hv.x * q[lane * 2] + hv.y * q[lane * 2 + 1];
#pragma unroll
        for (int off = 16; off; off >>= 1) e += __shfl_xor_sync(0xFFFFFFFFu, e, off);
        if (lane == 0) g_e[n] = e;
        wmax = fmaxf(wmax, e);
    }
    if (lane == 0) red[warp] = wmax;
    __syncthreads();
    if (tid == 0) {
        float m = red[0];
        for (int w = 1; w < 8; w++) m = fmaxf(m, red[w]);
        smax = m;
    }
    __syncthreads();
    float m = smax;
    // phase 2: exp + sum (thread-strided)
    float ps = 0.0f;
    for (int n = gs + tid; n < ge; n += 256) {
        float ex = expf(g_e[n] - m);
        g_e[n] = ex;
        ps += ex;
    }
#pragma unroll
    for (int off = 16; off; off >>= 1) ps += __shfl_xor_sync(0xFFFFFFFFu, ps, off);
    if (lane == 0) red[warp] = ps;
    __syncthreads();
    if (tid == 0) {
        float s = 0.0f;
        for (int w = 0; w < 8; w++) s += red[w];
        ssum_s = s;
    }
    __syncthreads();
    float inv = 1.0f / (ssum_s + 1e-16f);
    // phase 3: weighted sum (warp per node)
    float rx = 0.0f, ry = 0.0f;
    for (int n = gs + warp; n < ge; n += 8) {
        float a = g_e[n] * inv;
        float2 hv = *(const float2*)&g_h2[n * H2 + lane * 2];
        rx = fmaf(a, hv.x, rx);
        ry = fmaf(a, hv.y, ry);
    }
    rbuf[warp * H2 + lane * 2]     = rx;
    rbuf[warp * H2 + lane * 2 + 1] = ry;
    __syncthreads();
    if (tid < H2) {
        float r = 0.0f;
        for (int w = 0; w < 8; w++) r += rbuf[w * H2 + tid];
        g_qstar[g * 2 * H2 + H2 + tid] = r;   // r part of q_star
    }
}

// ---------------- final MLP: z = fc2(gelu(fc1(q_star))) ----------------
__global__ void __launch_bounds__(256) k_final(const float* __restrict__ fc1W, const float* __restrict__ fc1b,
                        const float* __restrict__ fc2W, const float* __restrict__ fc2b,
                        float* __restrict__ z) {
    int g = blockIdx.x * (blockDim.x >> 5) + (threadIdx.x >> 5);
    int lane = threadIdx.x & 31;
    if (g >= NG) return;
    const float* qr = &g_qstar[g * 2 * H2];
    float acc = fc1b[lane];
    const float* wr = &fc1W[lane * 2 * H2];
#pragma unroll 16
    for (int k = 0; k < 2 * H2; k++) acc = fmaf(wr[k], qr[k], acc);
    acc = gelu_f(acc);
    float v = acc * fc2W[lane];
#pragma unroll
    for (int off = 16; off; off >>= 1) v += __shfl_xor_sync(0xFFFFFFFFu, v, off);
    if (lane == 0) z[g] = v + fc2b[0];
}

// ---------------- host ----------------
extern "C" void kernel_launch(void* const* d_in, const int* in_sizes, int n_in,
                              void* d_out, int out_size) {
    const float* x       = (const float*)d_in[0];
    const int*   ei      = (const int*)d_in[1];
    const int*   batch   = (const int*)d_in[2];
    const float* nfcW    = (const float*)d_in[3];
    const float* nfcb    = (const float*)d_in[4];
    const float* gc1W    = (const float*)d_in[5];
    const float* gc1b    = (const float*)d_in[6];
    const float* gc2W    = (const float*)d_in[7];
    const float* gc2b    = (const float*)d_in[8];
    const float* l0Wih   = (const float*)d_in[9];
    const float* l0Whh   = (const float*)d_in[10];
    const float* l0bih   = (const float*)d_in[11];
    const float* l0bhh   = (const float*)d_in[12];
    const float* l1Wih   = (const float*)d_in[13];
    const float* l1Whh   = (const float*)d_in[14];
    const float* l1bih   = (const float*)d_in[15];
    const float* l1bhh   = (const float*)d_in[16];
    const float* fc1W    = (const float*)d_in[17];
    const float* fc1b    = (const float*)d_in[18];
    const float* fc2W    = (const float*)d_in[19];
    const float* fc2b    = (const float*)d_in[20];

    float* out = (float*)d_out;
    float* out_h = (out_size >= 512 + NN * H2) ? (out + 512) : nullptr;

    size_t sm_nfc   = (size_t)(NF * H1 + 8 * NF) * 4;     // 34 KB
    size_t sm_conv1 = (size_t)(H1 * H1 + 8 * H1) * 4;     // 68 KB
    size_t sm_conv2 = (size_t)(H1 * H2 + 8 * H1) * 4;     // 36 KB
    static int attr_done = 0;
    if (!attr_done) {
        cudaFuncSetAttribute(k_nfc,   cudaFuncAttributeMaxDynamicSharedMemorySize, (int)sm_nfc);
        cudaFuncSetAttribute(k_conv1, cudaFuncAttributeMaxDynamicSharedMemorySize, (int)sm_conv1);
        cudaFuncSetAttribute(k_conv2, cudaFuncAttributeMaxDynamicSharedMemorySize, (int)sm_conv2);
        attr_done = 1;
    }

    k_zero<<<256, 256>>>();
    k_nfc<<<(NN + 7) / 8, 256, sm_nfc>>>(x, nfcW, nfcb);
    k_count<<<(NE + 255) / 256, 256>>>(ei);
    k_scan<<<1, 256>>>();
    k_scatter<<<(NE + 255) / 256, 256>>>(ei);
    k_gstart<<<(NN + 255) / 256, 256>>>(batch);
    k_conv1<<<(NN + 7) / 8, 256, sm_conv1>>>(gc1W, gc1b);
    k_conv2<<<(NN + 7) / 8, 256, sm_conv2>>>(gc2W, gc2b, out_h);
    for (int s = 0; s < 4; s++) {
        k_lstm<<<NG / 8, 256>>>(l0Wih, l0Whh, l0bih, l0bhh, l1Wih, l1Whh, l1bih, l1bhh);
        k_attn<<<NG, 256>>>();
    }
    k_final<<<NG / 8, 256>>>(fc1W, fc1b, fc2W, fc2b, out);
}

// round 5
// speedup vs baseline: 3.2165x; 3.2165x over previous
#include <cuda_runtime.h>
#include <math.h>

#define NN 100000
#define NE 1600000
#define NG 512
#define NF 64
#define H1 128
#define H2 64
#define NBLK 98   // scan blocks: ceil(NN/1024)

// ---------------- device scratch ----------------
__device__ float g_h1[NN * H1];      // after nfc (conv1 input)
__device__ float g_s1[NN * H1];      // conv1 output
__device__ float g_h2[NN * H2];      // conv2 output (normalized)
__device__ float g_e[NN];            // attention logits / exp
__device__ int   g_cnt[NN];
__device__ int   g_off[NN + 1];
__device__ int   g_cur[NN];
__device__ int   g_csr[NE];          // src node per incoming-edge slot (keyed by dst)
__device__ int   g_gs[NG + 1];       // graph start offsets (batch is sorted)
__device__ int   g_bsum[128];
__device__ int   g_bpre[128];

__device__ __forceinline__ float gelu_f(float x) {
    return 0.5f * x * (1.0f + erff(x * 0.70710678118654752f));
}
__device__ __forceinline__ float sigmoid_f(float x) {
    return 1.0f / (1.0f + expf(-x));
}

// ---------------- init ----------------
__global__ void __launch_bounds__(256) k_zero() {
    int i = blockIdx.x * blockDim.x + threadIdx.x;
    int T = gridDim.x * blockDim.x;
    for (int j = i; j < NN; j += T) { g_cnt[j] = 0; g_cur[j] = 0; }
}

// ---------------- CSR build ----------------
__global__ void __launch_bounds__(256) k_count(const int* __restrict__ ei) {
    int e = blockIdx.x * blockDim.x + threadIdx.x;
    if (e < NE) atomicAdd(&g_cnt[ei[NE + e]], 1);
}

// 3-phase parallel scan: per-block scan + block sums; scan of sums; add-back.
__global__ void __launch_bounds__(256) k_scanA() {
    __shared__ int sm[256];
    int tid = threadIdx.x;
    int idx = blockIdx.x * 1024 + tid * 4;
    int v0 = 0, v1 = 0, v2 = 0, v3 = 0;
    if (idx     < NN) v0 = g_cnt[idx];
    if (idx + 1 < NN) v1 = g_cnt[idx + 1];
    if (idx + 2 < NN) v2 = g_cnt[idx + 2];
    if (idx + 3 < NN) v3 = g_cnt[idx + 3];
    int t = v0 + v1 + v2 + v3;
    sm[tid] = t;
    __syncthreads();
    for (int off = 1; off < 256; off <<= 1) {
        int u = (tid >= off) ? sm[tid - off] : 0;
        __syncthreads();
        sm[tid] += u;
        __syncthreads();
    }
    int excl = sm[tid] - t;
    if (idx     < NN) g_off[idx]     = excl;
    if (idx + 1 < NN) g_off[idx + 1] = excl + v0;
    if (idx + 2 < NN) g_off[idx + 2] = excl + v0 + v1;
    if (idx + 3 < NN) g_off[idx + 3] = excl + v0 + v1 + v2;
    if (tid == 255) g_bsum[blockIdx.x] = sm[255];
}

__global__ void __launch_bounds__(128) k_scanB() {
    __shared__ int sm[128];
    int tid = threadIdx.x;
    int t = (tid < NBLK) ? g_bsum[tid] : 0;
    sm[tid] = t;
    __syncthreads();
    for (int off = 1; off < 128; off <<= 1) {
        int u = (tid >= off) ? sm[tid - off] : 0;
        __syncthreads();
        sm[tid] += u;
        __syncthreads();
    }
    if (tid < NBLK) g_bpre[tid] = sm[tid] - t;
    if (tid == 0) g_off[NN] = NE;
}

__global__ void __launch_bounds__(256) k_scanC() {
    int add = g_bpre[blockIdx.x];
    int idx = blockIdx.x * 1024 + threadIdx.x * 4;
#pragma unroll
    for (int i = 0; i < 4; i++)
        if (idx + i < NN) g_off[idx + i] += add;
}

__global__ void __launch_bounds__(256) k_scatter(const int* __restrict__ ei) {
    int e = blockIdx.x * blockDim.x + threadIdx.x;
    if (e < NE) {
        int s = ei[e];
        int d = ei[NE + e];
        int pos = atomicAdd(&g_cur[d], 1);
        g_csr[g_off[d] + pos] = s;
    }
}

__global__ void __launch_bounds__(256) k_gstart(const int* __restrict__ batch) {
    int n = blockIdx.x * blockDim.x + threadIdx.x;
    if (n < NN) {
        int b = batch[n];
        int bp = (n == 0) ? -1 : batch[n - 1];
        for (int g = bp + 1; g <= b; g++) g_gs[g] = n;
        if (n == NN - 1)
            for (int g = b + 1; g <= NG; g++) g_gs[g] = NN;
    }
}

// ---------------- nfc: h = gelu(x @ W.T + b), 32 nodes/block ----------------
__global__ void __launch_bounds__(256) k_nfc(const float* __restrict__ x,
                                             const float* __restrict__ W,
                                             const float* __restrict__ b) {
    extern __shared__ float sm[];
    float* wt = sm;                 // [64][128] transposed
    float* xs = sm + NF * H1;       // [32][64]
    int tid = threadIdx.x;
    for (int i = tid; i < H1 * NF; i += 256) {
        int o = i >> 6, k = i & 63;
        wt[k * H1 + o] = W[i];
    }
    int warp = tid >> 5, lane = tid & 31;
    int nb = blockIdx.x * 32;
#pragma unroll
    for (int t = 0; t < 4; t++) {
        int row = warp * 4 + t;
        int n = nb + row;
        float2 xv = *(const float2*)&x[n * NF + lane * 2];
        *(float2*)&xs[row * NF + lane * 2] = xv;
    }
    __syncthreads();
    float4 bias = *(const float4*)&b[lane * 4];
    for (int t = 0; t < 4; t++) {
        int row = warp * 4 + t;
        float4 acc = bias;
        const float* xr = &xs[row * NF];
#pragma unroll 8
        for (int k = 0; k < NF; k++) {
            float xk = xr[k];
            float4 w = *(const float4*)&wt[k * H1 + lane * 4];
            acc.x = fmaf(xk, w.x, acc.x);
            acc.y = fmaf(xk, w.y, acc.y);
            acc.z = fmaf(xk, w.z, acc.z);
            acc.w = fmaf(xk, w.w, acc.w);
        }
        acc.x = gelu_f(acc.x); acc.y = gelu_f(acc.y);
        acc.z = gelu_f(acc.z); acc.w = gelu_f(acc.w);
        *(float4*)&g_h1[(nb + row) * H1 + lane * 4] = acc;
    }
}

// ---------------- conv1: gather+self, GEMM 128x128, gelu, 32 nodes/block ----------------
__global__ void __launch_bounds__(256) k_conv1(const float* __restrict__ W,
                                               const float* __restrict__ b) {
    extern __shared__ float sm[];
    float* wt  = sm;                 // [128][128] transposed (64 KB)
    float* agg = sm + H1 * H1;       // [32][128] (16 KB)
    int tid = threadIdx.x;
    for (int i = tid; i < H1 * H1; i += 256) {
        int o = i >> 7, k = i & 127;
        wt[k * H1 + o] = W[i];
    }
    int warp = tid >> 5, lane = tid & 31;
    int nb = blockIdx.x * 32;
    for (int t = 0; t < 4; t++) {
        int row = warp * 4 + t;
        int n = nb + row;
        float4 a = *(const float4*)&g_h1[n * H1 + lane * 4];   // self
        int e0 = g_off[n], e1 = g_off[n + 1];
        int j = e0;
        for (; j + 3 < e1; j += 4) {
            int s0 = g_csr[j], s1 = g_csr[j + 1], s2 = g_csr[j + 2], s3 = g_csr[j + 3];
            float4 v0 = *(const float4*)&g_h1[s0 * H1 + lane * 4];
            float4 v1 = *(const float4*)&g_h1[s1 * H1 + lane * 4];
            float4 v2 = *(const float4*)&g_h1[s2 * H1 + lane * 4];
            float4 v3 = *(const float4*)&g_h1[s3 * H1 + lane * 4];
            a.x += (v0.x + v1.x) + (v2.x + v3.x);
            a.y += (v0.y + v1.y) + (v2.y + v3.y);
            a.z += (v0.z + v1.z) + (v2.z + v3.z);
            a.w += (v0.w + v1.w) + (v2.w + v3.w);
        }
        for (; j < e1; j++) {
            int s0 = g_csr[j];
            float4 v0 = *(const float4*)&g_h1[s0 * H1 + lane * 4];
            a.x += v0.x; a.y += v0.y; a.z += v0.z; a.w += v0.w;
        }
        *(float4*)&agg[row * H1 + lane * 4] = a;
    }
    __syncthreads();
    float4 bias = *(const float4*)&b[lane * 4];
    for (int t = 0; t < 4; t++) {
        int row = warp * 4 + t;
        float4 acc = bias;
        const float* sr = &agg[row * H1];
#pragma unroll 8
        for (int k = 0; k < H1; k++) {
            float sk = sr[k];
            float4 w = *(const float4*)&wt[k * H1 + lane * 4];
            acc.x = fmaf(sk, w.x, acc.x);
            acc.y = fmaf(sk, w.y, acc.y);
            acc.z = fmaf(sk, w.z, acc.z);
            acc.w = fmaf(sk, w.w, acc.w);
        }
        acc.x = gelu_f(acc.x); acc.y = gelu_f(acc.y);
        acc.z = gelu_f(acc.z); acc.w = gelu_f(acc.w);
        *(float4*)&g_s1[(nb + row) * H1 + lane * 4] = acc;
    }
}

// ---------------- conv2: gather+self, GEMM 128->64, gelu, normalize ----------------
__global__ void __launch_bounds__(256) k_conv2(const float* __restrict__ W,
                                               const float* __restrict__ b,
                                               float* __restrict__ out_h) {
    extern __shared__ float sm[];
    float* wt  = sm;                 // [128][64] transposed (32 KB)
    float* agg = sm + H1 * H2;       // [32][128] (16 KB)
    int tid = threadIdx.x;
    for (int i = tid; i < H2 * H1; i += 256) {
        int o = i >> 7, k = i & 127;
        wt[k * H2 + o] = W[i];
    }
    int warp = tid >> 5, lane = tid & 31;
    int nb = blockIdx.x * 32;
    for (int t = 0; t < 4; t++) {
        int row = warp * 4 + t;
        int n = nb + row;
        float4 a = *(const float4*)&g_s1[n * H1 + lane * 4];
        int e0 = g_off[n], e1 = g_off[n + 1];
        int j = e0;
        for (; j + 3 < e1; j += 4) {
            int s0 = g_csr[j], s1 = g_csr[j + 1], s2 = g_csr[j + 2], s3 = g_csr[j + 3];
            float4 v0 = *(const float4*)&g_s1[s0 * H1 + lane * 4];
            float4 v1 = *(const float4*)&g_s1[s1 * H1 + lane * 4];
            float4 v2 = *(const float4*)&g_s1[s2 * H1 + lane * 4];
            float4 v3 = *(const float4*)&g_s1[s3 * H1 + lane * 4];
            a.x += (v0.x + v1.x) + (v2.x + v3.x);
            a.y += (v0.y + v1.y) + (v2.y + v3.y);
            a.z += (v0.z + v1.z) + (v2.z + v3.z);
            a.w += (v0.w + v1.w) + (v2.w + v3.w);
        }
        for (; j < e1; j++) {
            int s0 = g_csr[j];
            float4 v0 = *(const float4*)&g_s1[s0 * H1 + lane * 4];
            a.x += v0.x; a.y += v0.y; a.z += v0.z; a.w += v0.w;
        }
        *(float4*)&agg[row * H1 + lane * 4] = a;
    }
    __syncthreads();
    float2 bias = *(const float2*)&b[lane * 2];
    for (int t = 0; t < 4; t++) {
        int row = warp * 4 + t;
        float2 acc = bias;
        const float* sr = &agg[row * H1];
#pragma unroll 8
        for (int k = 0; k < H1; k++) {
            float sk = sr[k];
            float2 w = *(const float2*)&wt[k * H2 + lane * 2];
            acc.x = fmaf(sk, w.x, acc.x);
            acc.y = fmaf(sk, w.y, acc.y);
        }
        acc.x = gelu_f(acc.x);
        acc.y = gelu_f(acc.y);
        float ssq = acc.x * acc.x + acc.y * acc.y;
#pragma unroll
        for (int off = 16; off; off >>= 1) ssq += __shfl_xor_sync(0xFFFFFFFFu, ssq, off);
        float inv = 1.0f / fmaxf(sqrtf(ssq), 1e-12f);
        acc.x *= inv; acc.y *= inv;
        int n = nb + row;
        *(float2*)&g_h2[n * H2 + lane * 2] = acc;
        if (out_h) *(float2*)&out_h[n * H2 + lane * 2] = acc;
    }
}

// ---------------- fused Set2Set (4 steps) + final MLP: one block per graph ----------------
__global__ void __launch_bounds__(256) k_s2s(
        const float* __restrict__ Wih0, const float* __restrict__ Whh0,
        const float* __restrict__ bih0, const float* __restrict__ bhh0,
        const float* __restrict__ Wih1, const float* __restrict__ Whh1,
        const float* __restrict__ bih1, const float* __restrict__ bhh1,
        const float* __restrict__ fc1W, const float* __restrict__ fc1b,
        const float* __restrict__ fc2W, const float* __restrict__ fc2b,
        float* __restrict__ z) {
    __shared__ float h0[H2], c0[H2], h1[H2], c1[H2], qs[2 * H2];
    __shared__ float gb[4 * H2], red[8], rbuf[8 * H2];
    __shared__ float smax, ssum;
    int g = blockIdx.x;
    int tid = threadIdx.x, warp = tid >> 5, lane = tid & 31;
    int gs = g_gs[g], ge = g_gs[g + 1];
    if (tid < H2) { h0[tid] = 0.0f; c0[tid] = 0.0f; h1[tid] = 0.0f; c1[tid] = 0.0f; }
    if (tid < 2 * H2) qs[tid] = 0.0f;
    __syncthreads();

    for (int step = 0; step < 4; step++) {
        // ---- LSTM layer 0: 256 gate rows, warp per row (coalesced W reads)
        for (int r = warp; r < 4 * H2; r += 8) {
            const float* wi = &Wih0[r * 2 * H2];
            float p = wi[lane] * qs[lane] + wi[lane + 32] * qs[lane + 32]
                    + wi[lane + 64] * qs[lane + 64] + wi[lane + 96] * qs[lane + 96];
            const float* wh = &Whh0[r * H2];
            p += wh[lane] * h0[lane] + wh[lane + 32] * h0[lane + 32];
#pragma unroll
            for (int off = 16; off; off >>= 1) p += __shfl_xor_sync(0xFFFFFFFFu, p, off);
            if (lane == 0) gb[r] = p + bih0[r] + bhh0[r];
        }
        __syncthreads();
        if (tid < H2) {
            float i = sigmoid_f(gb[tid]);
            float f = sigmoid_f(gb[H2 + tid]);
            float gg = tanhf(gb[2 * H2 + tid]);
            float o = sigmoid_f(gb[3 * H2 + tid]);
            float c = f * c0[tid] + i * gg;
            c0[tid] = c;
            h0[tid] = o * tanhf(c);
        }
        __syncthreads();
        // ---- LSTM layer 1
        for (int r = warp; r < 4 * H2; r += 8) {
            const float* wi = &Wih1[r * H2];
            float p = wi[lane] * h0[lane] + wi[lane + 32] * h0[lane + 32];
            const float* wh = &Whh1[r * H2];
            p += wh[lane] * h1[lane] + wh[lane + 32] * h1[lane + 32];
#pragma unroll
            for (int off = 16; off; off >>= 1) p += __shfl_xor_sync(0xFFFFFFFFu, p, off);
            if (lane == 0) gb[r] = p + bih1[r] + bhh1[r];
        }
        __syncthreads();
        if (tid < H2) {
            float i = sigmoid_f(gb[tid]);
            float f = sigmoid_f(gb[H2 + tid]);
            float gg = tanhf(gb[2 * H2 + tid]);
            float o = sigmoid_f(gb[3 * H2 + tid]);
            float c = f * c1[tid] + i * gg;
            c1[tid] = c;
            float h = o * tanhf(c);
            h1[tid] = h;
            qs[tid] = h;            // q part of next q_star
        }
        __syncthreads();
        // ---- attention: phase 1 (logits + max), warp per node
        float wmax = -3.4e38f;
        for (int n = gs + warp; n < ge; n += 8) {
            float2 hv = *(const float2*)&g_h2[n * H2 + lane * 2];
            float e = hv.x * qs[lane * 2] + hv.y * qs[lane * 2 + 1];
#pragma unroll
            for (int off = 16; off; off >>= 1) e += __shfl_xor_sync(0xFFFFFFFFu, e, off);
            if (lane == 0) g_e[n] = e;
            wmax = fmaxf(wmax, e);
        }
        if (lane == 0) red[warp] = wmax;
        __syncthreads();
        if (tid == 0) {
            float m = red[0];
            for (int w = 1; w < 8; w++) m = fmaxf(m, red[w]);
            smax = m;
        }
        __syncthreads();
        float m = smax;
        // ---- phase 2: exp + sum
        float ps = 0.0f;
        for (int n = gs + tid; n < ge; n += 256) {
            float ex = expf(g_e[n] - m);
            g_e[n] = ex;
            ps += ex;
        }
#pragma unroll
        for (int off = 16; off; off >>= 1) ps += __shfl_xor_sync(0xFFFFFFFFu, ps, off);
        if (lane == 0) red[warp] = ps;
        __syncthreads();
        if (tid == 0) {
            float s = 0.0f;
            for (int w = 0; w < 8; w++) s += red[w];
            ssum = s;
        }
        __syncthreads();
        float inv = 1.0f / (ssum + 1e-16f);
        // ---- phase 3: weighted sum
        float rx = 0.0f, ry = 0.0f;
        for (int n = gs + warp; n < ge; n += 8) {
            float a = g_e[n] * inv;
            float2 hv = *(const float2*)&g_h2[n * H2 + lane * 2];
            rx = fmaf(a, hv.x, rx);
            ry = fmaf(a, hv.y, ry);
        }
        rbuf[warp * H2 + lane * 2]     = rx;
        rbuf[warp * H2 + lane * 2 + 1] = ry;
        __syncthreads();
        if (tid < H2) {
            float r = 0.0f;
            for (int w = 0; w < 8; w++) r += rbuf[w * H2 + tid];
            qs[H2 + tid] = r;       // r part of next q_star
        }
        __syncthreads();
    }

    // ---- final MLP: z = fc2(gelu(fc1(q_star)))
    for (int r = warp; r < 32; r += 8) {
        const float* wr = &fc1W[r * 2 * H2];
        float p = wr[lane] * qs[lane] + wr[lane + 32] * qs[lane + 32]
                + wr[lane + 64] * qs[lane + 64] + wr[lane + 96] * qs[lane + 96];
#pragma unroll
        for (int off = 16; off; off >>= 1) p += __shfl_xor_sync(0xFFFFFFFFu, p, off);
        if (lane == 0) gb[r] = gelu_f(p + fc1b[r]);
    }
    __syncthreads();
    if (warp == 0) {
        float v = gb[lane] * fc2W[lane];
#pragma unroll
        for (int off = 16; off; off >>= 1) v += __shfl_xor_sync(0xFFFFFFFFu, v, off);
        if (lane == 0) z[g] = v + fc2b[0];
    }
}

// ---------------- host ----------------
extern "C" void kernel_launch(void* const* d_in, const int* in_sizes, int n_in,
                              void* d_out, int out_size) {
    const float* x     = (const float*)d_in[0];
    const int*   ei    = (const int*)d_in[1];
    const int*   batch = (const int*)d_in[2];
    const float* nfcW  = (const float*)d_in[3];
    const float* nfcb  = (const float*)d_in[4];
    const float* gc1W  = (const float*)d_in[5];
    const float* gc1b  = (const float*)d_in[6];
    const float* gc2W  = (const float*)d_in[7];
    const float* gc2b  = (const float*)d_in[8];
    const float* l0Wih = (const float*)d_in[9];
    const float* l0Whh = (const float*)d_in[10];
    const float* l0bih = (const float*)d_in[11];
    const float* l0bhh = (const float*)d_in[12];
    const float* l1Wih = (const float*)d_in[13];
    const float* l1Whh = (const float*)d_in[14];
    const float* l1bih = (const float*)d_in[15];
    const float* l1bhh = (const float*)d_in[16];
    const float* fc1W  = (const float*)d_in[17];
    const float* fc1b  = (const float*)d_in[18];
    const float* fc2W  = (const float*)d_in[19];
    const float* fc2b  = (const float*)d_in[20];

    float* out = (float*)d_out;
    float* out_h = (out_size >= NG + NN * H2) ? (out + NG) : nullptr;

    size_t sm_nfc   = (size_t)(NF * H1 + 32 * NF) * 4;    // 40 KB
    size_t sm_conv1 = (size_t)(H1 * H1 + 32 * H1) * 4;    // 80 KB
    size_t sm_conv2 = (size_t)(H1 * H2 + 32 * H1) * 4;    // 48 KB
    cudaFuncSetAttribute(k_nfc,   cudaFuncAttributeMaxDynamicSharedMemorySize, (int)sm_nfc);
    cudaFuncSetAttribute(k_conv1, cudaFuncAttributeMaxDynamicSharedMemorySize, (int)sm_conv1);
    cudaFuncSetAttribute(k_conv2, cudaFuncAttributeMaxDynamicSharedMemorySize, (int)sm_conv2);

    k_zero<<<256, 256>>>();
    k_count<<<(NE + 255) / 256, 256>>>(ei);
    k_scanA<<<NBLK, 256>>>();
    k_scanB<<<1, 128>>>();
    k_scanC<<<NBLK, 256>>>();
    k_scatter<<<(NE + 255) / 256, 256>>>(ei);
    k_gstart<<<(NN + 255) / 256, 256>>>(batch);
    k_nfc<<<NN / 32, 256, sm_nfc>>>(x, nfcW, nfcb);
    k_conv1<<<NN / 32, 256, sm_conv1>>>(gc1W, gc1b);
    k_conv2<<<NN / 32, 256, sm_conv2>>>(gc2W, gc2b, out_h);
    k_s2s<<<NG, 256>>>(l0Wih, l0Whh, l0bih, l0bhh,
                       l1Wih, l1Whh, l1bih, l1bhh,
                       fc1W, fc1b, fc2W, fc2b, out);
}

// round 6
// speedup vs baseline: 3.9849x; 1.2389x over previous
#include <cuda_runtime.h>
#include <math.h>

#define NN 100000
#define NE 1600000
#define NG 512
#define NF 64
#define H1 128
#define H2 64
#define NBLK 98   // scan blocks: ceil(NN/1024)

// ---------------- device scratch ----------------
__device__ float g_h1[NN * H1];      // after nfc (conv1 input)
__device__ float g_s1[NN * H1];      // conv1 output
__device__ float g_h2[NN * H2];      // conv2 output (normalized)
__device__ float g_e[NN];            // attention logits / exp
__device__ int   g_cnt[NN];
__device__ int   g_off[NN + 1];
__device__ int   g_cur[NN];
__device__ int   g_csr[NE];          // src node per incoming-edge slot (keyed by dst)
__device__ int   g_gs[NG + 1];       // graph start offsets (batch is sorted)
__device__ int   g_bsum[128];
__device__ int   g_bpre[128];

__device__ __forceinline__ float gelu_f(float x) {
    return 0.5f * x * (1.0f + erff(x * 0.70710678118654752f));
}
__device__ __forceinline__ float sigmoid_f(float x) {
    return 1.0f / (1.0f + expf(-x));
}

// ---------------- init ----------------
__global__ void __launch_bounds__(256) k_zero() {
    int i = blockIdx.x * blockDim.x + threadIdx.x;
    int T = gridDim.x * blockDim.x;
    for (int j = i; j < NN; j += T) { g_cnt[j] = 0; g_cur[j] = 0; }
}

// ---------------- CSR build ----------------
__global__ void __launch_bounds__(256) k_count(const int* __restrict__ ei) {
    int e = blockIdx.x * blockDim.x + threadIdx.x;
    if (e < NE) atomicAdd(&g_cnt[ei[NE + e]], 1);
}

__global__ void __launch_bounds__(256) k_scanA() {
    __shared__ int sm[256];
    int tid = threadIdx.x;
    int idx = blockIdx.x * 1024 + tid * 4;
    int v0 = 0, v1 = 0, v2 = 0, v3 = 0;
    if (idx     < NN) v0 = g_cnt[idx];
    if (idx + 1 < NN) v1 = g_cnt[idx + 1];
    if (idx + 2 < NN) v2 = g_cnt[idx + 2];
    if (idx + 3 < NN) v3 = g_cnt[idx + 3];
    int t = v0 + v1 + v2 + v3;
    sm[tid] = t;
    __syncthreads();
    for (int off = 1; off < 256; off <<= 1) {
        int u = (tid >= off) ? sm[tid - off] : 0;
        __syncthreads();
        sm[tid] += u;
        __syncthreads();
    }
    int excl = sm[tid] - t;
    if (idx     < NN) g_off[idx]     = excl;
    if (idx + 1 < NN) g_off[idx + 1] = excl + v0;
    if (idx + 2 < NN) g_off[idx + 2] = excl + v0 + v1;
    if (idx + 3 < NN) g_off[idx + 3] = excl + v0 + v1 + v2;
    if (tid == 255) g_bsum[blockIdx.x] = sm[255];
}

__global__ void __launch_bounds__(128) k_scanB() {
    __shared__ int sm[128];
    int tid = threadIdx.x;
    int t = (tid < NBLK) ? g_bsum[tid] : 0;
    sm[tid] = t;
    __syncthreads();
    for (int off = 1; off < 128; off <<= 1) {
        int u = (tid >= off) ? sm[tid - off] : 0;
        __syncthreads();
        sm[tid] += u;
        __syncthreads();
    }
    if (tid < NBLK) g_bpre[tid] = sm[tid] - t;
    if (tid == 0) g_off[NN] = NE;
}

__global__ void __launch_bounds__(256) k_scanC() {
    int add = g_bpre[blockIdx.x];
    int idx = blockIdx.x * 1024 + threadIdx.x * 4;
#pragma unroll
    for (int i = 0; i < 4; i++)
        if (idx + i < NN) g_off[idx + i] += add;
}

__global__ void __launch_bounds__(256) k_scatter(const int* __restrict__ ei) {
    int e = blockIdx.x * blockDim.x + threadIdx.x;
    if (e < NE) {
        int s = ei[e];
        int d = ei[NE + e];
        int pos = atomicAdd(&g_cur[d], 1);
        g_csr[g_off[d] + pos] = s;
    }
}

__global__ void __launch_bounds__(256) k_gstart(const int* __restrict__ batch) {
    int n = blockIdx.x * blockDim.x + threadIdx.x;
    if (n < NN) {
        int b = batch[n];
        int bp = (n == 0) ? -1 : batch[n - 1];
        for (int g = bp + 1; g <= b; g++) g_gs[g] = n;
        if (n == NN - 1)
            for (int g = b + 1; g <= NG; g++) g_gs[g] = NN;
    }
}

// ---------------- nfc: h = gelu(x @ W.T + b), 32 nodes/block, 4-row weight reuse ----------------
__global__ void __launch_bounds__(256) k_nfc(const float* __restrict__ x,
                                             const float* __restrict__ W,
                                             const float* __restrict__ b) {
    extern __shared__ float sm[];
    float* wt = sm;                 // [64][128] transposed
    float* xs = sm + NF * H1;       // [32][64]
    int tid = threadIdx.x;
    for (int i = tid; i < H1 * NF; i += 256) {
        int o = i >> 6, k = i & 63;
        wt[k * H1 + o] = W[i];
    }
    int warp = tid >> 5, lane = tid & 31;
    int nb = blockIdx.x * 32;
#pragma unroll
    for (int t = 0; t < 4; t++) {
        int row = warp * 4 + t;
        float2 xv = *(const float2*)&x[(nb + row) * NF + lane * 2];
        *(float2*)&xs[row * NF + lane * 2] = xv;
    }
    __syncthreads();
    float4 bias = *(const float4*)&b[lane * 4];
    float4 a0 = bias, a1 = bias, a2 = bias, a3 = bias;
    const float* x0 = &xs[(warp * 4 + 0) * NF];
    const float* x1 = &xs[(warp * 4 + 1) * NF];
    const float* x2 = &xs[(warp * 4 + 2) * NF];
    const float* x3 = &xs[(warp * 4 + 3) * NF];
#pragma unroll 4
    for (int k = 0; k < NF; k++) {
        float4 w = *(const float4*)&wt[k * H1 + lane * 4];
        float v0 = x0[k], v1 = x1[k], v2 = x2[k], v3 = x3[k];
        a0.x = fmaf(v0, w.x, a0.x); a0.y = fmaf(v0, w.y, a0.y);
        a0.z = fmaf(v0, w.z, a0.z); a0.w = fmaf(v0, w.w, a0.w);
        a1.x = fmaf(v1, w.x, a1.x); a1.y = fmaf(v1, w.y, a1.y);
        a1.z = fmaf(v1, w.z, a1.z); a1.w = fmaf(v1, w.w, a1.w);
        a2.x = fmaf(v2, w.x, a2.x); a2.y = fmaf(v2, w.y, a2.y);
        a2.z = fmaf(v2, w.z, a2.z); a2.w = fmaf(v2, w.w, a2.w);
        a3.x = fmaf(v3, w.x, a3.x); a3.y = fmaf(v3, w.y, a3.y);
        a3.z = fmaf(v3, w.z, a3.z); a3.w = fmaf(v3, w.w, a3.w);
    }
    int base = (nb + warp * 4) * H1 + lane * 4;
    a0.x = gelu_f(a0.x); a0.y = gelu_f(a0.y); a0.z = gelu_f(a0.z); a0.w = gelu_f(a0.w);
    *(float4*)&g_h1[base] = a0;
    a1.x = gelu_f(a1.x); a1.y = gelu_f(a1.y); a1.z = gelu_f(a1.z); a1.w = gelu_f(a1.w);
    *(float4*)&g_h1[base + H1] = a1;
    a2.x = gelu_f(a2.x); a2.y = gelu_f(a2.y); a2.z = gelu_f(a2.z); a2.w = gelu_f(a2.w);
    *(float4*)&g_h1[base + 2 * H1] = a2;
    a3.x = gelu_f(a3.x); a3.y = gelu_f(a3.y); a3.z = gelu_f(a3.z); a3.w = gelu_f(a3.w);
    *(float4*)&g_h1[base + 3 * H1] = a3;
}

// ---------------- conv1: gather+self, GEMM 128x128, gelu, 4-row weight reuse ----------------
__global__ void __launch_bounds__(256) k_conv1(const float* __restrict__ W,
                                               const float* __restrict__ b) {
    extern __shared__ float sm[];
    float* wt  = sm;                 // [128][128] transposed (64 KB)
    float* agg = sm + H1 * H1;       // [32][128] (16 KB)
    int tid = threadIdx.x;
    for (int i = tid; i < H1 * H1; i += 256) {
        int o = i >> 7, k = i & 127;
        wt[k * H1 + o] = W[i];
    }
    int warp = tid >> 5, lane = tid & 31;
    int nb = blockIdx.x * 32;
    for (int t = 0; t < 4; t++) {
        int row = warp * 4 + t;
        int n = nb + row;
        float4 a = *(const float4*)&g_h1[n * H1 + lane * 4];   // self
        int e0 = g_off[n], e1 = g_off[n + 1];
        int j = e0;
        for (; j + 3 < e1; j += 4) {
            int s0 = g_csr[j], s1 = g_csr[j + 1], s2 = g_csr[j + 2], s3 = g_csr[j + 3];
            float4 v0 = *(const float4*)&g_h1[s0 * H1 + lane * 4];
            float4 v1 = *(const float4*)&g_h1[s1 * H1 + lane * 4];
            float4 v2 = *(const float4*)&g_h1[s2 * H1 + lane * 4];
            float4 v3 = *(const float4*)&g_h1[s3 * H1 + lane * 4];
            a.x += (v0.x + v1.x) + (v2.x + v3.x);
            a.y += (v0.y + v1.y) + (v2.y + v3.y);
            a.z += (v0.z + v1.z) + (v2.z + v3.z);
            a.w += (v0.w + v1.w) + (v2.w + v3.w);
        }
        for (; j < e1; j++) {
            int s0 = g_csr[j];
            float4 v0 = *(const float4*)&g_h1[s0 * H1 + lane * 4];
            a.x += v0.x; a.y += v0.y; a.z += v0.z; a.w += v0.w;
        }
        *(float4*)&agg[row * H1 + lane * 4] = a;
    }
    __syncthreads();
    float4 bias = *(const float4*)&b[lane * 4];
    float4 a0 = bias, a1 = bias, a2 = bias, a3 = bias;
    const float* r0 = &agg[(warp * 4 + 0) * H1];
    const float* r1 = &agg[(warp * 4 + 1) * H1];
    const float* r2 = &agg[(warp * 4 + 2) * H1];
    const float* r3 = &agg[(warp * 4 + 3) * H1];
#pragma unroll 4
    for (int k = 0; k < H1; k++) {
        float4 w = *(const float4*)&wt[k * H1 + lane * 4];
        float v0 = r0[k], v1 = r1[k], v2 = r2[k], v3 = r3[k];
        a0.x = fmaf(v0, w.x, a0.x); a0.y = fmaf(v0, w.y, a0.y);
        a0.z = fmaf(v0, w.z, a0.z); a0.w = fmaf(v0, w.w, a0.w);
        a1.x = fmaf(v1, w.x, a1.x); a1.y = fmaf(v1, w.y, a1.y);
        a1.z = fmaf(v1, w.z, a1.z); a1.w = fmaf(v1, w.w, a1.w);
        a2.x = fmaf(v2, w.x, a2.x); a2.y = fmaf(v2, w.y, a2.y);
        a2.z = fmaf(v2, w.z, a2.z); a2.w = fmaf(v2, w.w, a2.w);
        a3.x = fmaf(v3, w.x, a3.x); a3.y = fmaf(v3, w.y, a3.y);
        a3.z = fmaf(v3, w.z, a3.z); a3.w = fmaf(v3, w.w, a3.w);
    }
    int base = (nb + warp * 4) * H1 + lane * 4;
    a0.x = gelu_f(a0.x); a0.y = gelu_f(a0.y); a0.z = gelu_f(a0.z); a0.w = gelu_f(a0.w);
    *(float4*)&g_s1[base] = a0;
    a1.x = gelu_f(a1.x); a1.y = gelu_f(a1.y); a1.z = gelu_f(a1.z); a1.w = gelu_f(a1.w);
    *(float4*)&g_s1[base + H1] = a1;
    a2.x = gelu_f(a2.x); a2.y = gelu_f(a2.y); a2.z = gelu_f(a2.z); a2.w = gelu_f(a2.w);
    *(float4*)&g_s1[base + 2 * H1] = a2;
    a3.x = gelu_f(a3.x); a3.y = gelu_f(a3.y); a3.z = gelu_f(a3.z); a3.w = gelu_f(a3.w);
    *(float4*)&g_s1[base + 3 * H1] = a3;
}

// ---------------- conv2: gather+self, GEMM 128->64, gelu, normalize, 4-row reuse ----------------
__global__ void __launch_bounds__(256) k_conv2(const float* __restrict__ W,
                                               const float* __restrict__ b,
                                               float* __restrict__ out_h) {
    extern __shared__ float sm[];
    float* wt  = sm;                 // [128][64] transposed (32 KB)
    float* agg = sm + H1 * H2;       // [32][128] (16 KB)
    int tid = threadIdx.x;
    for (int i = tid; i < H2 * H1; i += 256) {
        int o = i >> 7, k = i & 127;
        wt[k * H2 + o] = W[i];
    }
    int warp = tid >> 5, lane = tid & 31;
    int nb = blockIdx.x * 32;
    for (int t = 0; t < 4; t++) {
        int row = warp * 4 + t;
        int n = nb + row;
        float4 a = *(const float4*)&g_s1[n * H1 + lane * 4];
        int e0 = g_off[n], e1 = g_off[n + 1];
        int j = e0;
        for (; j + 3 < e1; j += 4) {
            int s0 = g_csr[j], s1 = g_csr[j + 1], s2 = g_csr[j + 2], s3 = g_csr[j + 3];
            float4 v0 = *(const float4*)&g_s1[s0 * H1 + lane * 4];
            float4 v1 = *(const float4*)&g_s1[s1 * H1 + lane * 4];
            float4 v2 = *(const float4*)&g_s1[s2 * H1 + lane * 4];
            float4 v3 = *(const float4*)&g_s1[s3 * H1 + lane * 4];
            a.x += (v0.x + v1.x) + (v2.x + v3.x);
            a.y += (v0.y + v1.y) + (v2.y + v3.y);
            a.z += (v0.z + v1.z) + (v2.z + v3.z);
            a.w += (v0.w + v1.w) + (v2.w + v3.w);
        }
        for (; j < e1; j++) {
            int s0 = g_csr[j];
            float4 v0 = *(const float4*)&g_s1[s0 * H1 + lane * 4];
            a.x += v0.x; a.y += v0.y; a.z += v0.z; a.w += v0.w;
        }
        *(float4*)&agg[row * H1 + lane * 4] = a;
    }
    __syncthreads();
    float2 bias = *(const float2*)&b[lane * 2];
    float2 a0 = bias, a1 = bias, a2 = bias, a3 = bias;
    const float* r0 = &agg[(warp * 4 + 0) * H1];
    const float* r1 = &agg[(warp * 4 + 1) * H1];
    const float* r2 = &agg[(warp * 4 + 2) * H1];
    const float* r3 = &agg[(warp * 4 + 3) * H1];
#pragma unroll 4
    for (int k = 0; k < H1; k++) {
        float2 w = *(const float2*)&wt[k * H2 + lane * 2];
        float v0 = r0[k], v1 = r1[k], v2 = r2[k], v3 = r3[k];
        a0.x = fmaf(v0, w.x, a0.x); a0.y = fmaf(v0, w.y, a0.y);
        a1.x = fmaf(v1, w.x, a1.x); a1.y = fmaf(v1, w.y, a1.y);
        a2.x = fmaf(v2, w.x, a2.x); a2.y = fmaf(v2, w.y, a2.y);
        a3.x = fmaf(v3, w.x, a3.x); a3.y = fmaf(v3, w.y, a3.y);
    }
#pragma unroll
    for (int t = 0; t < 4; t++) {
        float2 acc = (t == 0) ? a0 : (t == 1) ? a1 : (t == 2) ? a2 : a3;
        acc.x = gelu_f(acc.x);
        acc.y = gelu_f(acc.y);
        float ssq = acc.x * acc.x + acc.y * acc.y;
#pragma unroll
        for (int off = 16; off; off >>= 1) ssq += __shfl_xor_sync(0xFFFFFFFFu, ssq, off);
        float inv = 1.0f / fmaxf(sqrtf(ssq), 1e-12f);
        acc.x *= inv; acc.y *= inv;
        int n = nb + warp * 4 + t;
        *(float2*)&g_h2[n * H2 + lane * 2] = acc;
        if (out_h) *(float2*)&out_h[n * H2 + lane * 2] = acc;
    }
}

// ---------------- fused Set2Set (4 steps) + final MLP: one block per graph ----------------
__global__ void __launch_bounds__(256) k_s2s(
        const float* __restrict__ Wih0, const float* __restrict__ Whh0,
        const float* __restrict__ bih0, const float* __restrict__ bhh0,
        const float* __restrict__ Wih1, const float* __restrict__ Whh1,
        const float* __restrict__ bih1, const float* __restrict__ bhh1,
        const float* __restrict__ fc1W, const float* __restrict__ fc1b,
        const float* __restrict__ fc2W, const float* __restrict__ fc2b,
        float* __restrict__ z) {
    __shared__ float h0[H2], c0[H2], h1[H2], c1[H2], qs[2 * H2];
    __shared__ float gb[4 * H2], red[8], rbuf[8 * H2];
    __shared__ float smax, ssum;
    int g = blockIdx.x;
    int tid = threadIdx.x, warp = tid >> 5, lane = tid & 31;
    int gs = g_gs[g], ge = g_gs[g + 1];
    if (tid < H2) { h0[tid] = 0.0f; c0[tid] = 0.0f; h1[tid] = 0.0f; c1[tid] = 0.0f; }
    if (tid < 2 * H2) qs[tid] = 0.0f;
    __syncthreads();

    for (int step = 0; step < 4; step++) {
        for (int r = warp; r < 4 * H2; r += 8) {
            const float* wi = &Wih0[r * 2 * H2];
            float p = wi[lane] * qs[lane] + wi[lane + 32] * qs[lane + 32]
                    + wi[lane + 64] * qs[lane + 64] + wi[lane + 96] * qs[lane + 96];
            const float* wh = &Whh0[r * H2];
            p += wh[lane] * h0[lane] + wh[lane + 32] * h0[lane + 32];
#pragma unroll
            for (int off = 16; off; off >>= 1) p += __shfl_xor_sync(0xFFFFFFFFu, p, off);
            if (lane == 0) gb[r] = p + bih0[r] + bhh0[r];
        }
        __syncthreads();
        if (tid < H2) {
            float i = sigmoid_f(gb[tid]);
            float f = sigmoid_f(gb[H2 + tid]);
            float gg = tanhf(gb[2 * H2 + tid]);
            float o = sigmoid_f(gb[3 * H2 + tid]);
            float c = f * c0[tid] + i * gg;
            c0[tid] = c;
            h0[tid] = o * tanhf(c);
        }
        __syncthreads();
        for (int r = warp; r < 4 * H2; r += 8) {
            const float* wi = &Wih1[r * H2];
            float p = wi[lane] * h0[lane] + wi[lane + 32] * h0[lane + 32];
            const float* wh = &Whh1[r * H2];
            p += wh[lane] * h1[lane] + wh[lane + 32] * h1[lane + 32];
#pragma unroll
            for (int off = 16; off; off >>= 1) p += __shfl_xor_sync(0xFFFFFFFFu, p, off);
            if (lane == 0) gb[r] = p + bih1[r] + bhh1[r];
        }
        __syncthreads();
        if (tid < H2) {
            float i = sigmoid_f(gb[tid]);
            float f = sigmoid_f(gb[H2 + tid]);
            float gg = tanhf(gb[2 * H2 + tid]);
            float o = sigmoid_f(gb[3 * H2 + tid]);
            float c = f * c1[tid] + i * gg;
            c1[tid] = c;
            float h = o * tanhf(c);
            h1[tid] = h;
            qs[tid] = h;
        }
        __syncthreads();
        float wmax = -3.4e38f;
        for (int n = gs + warp; n < ge; n += 8) {
            float2 hv = *(const float2*)&g_h2[n * H2 + lane * 2];
            float e = hv.x * qs[lane * 2] + hv.y * qs[lane * 2 + 1];
#pragma unroll
            for (int off = 16; off; off >>= 1) e += __shfl_xor_sync(0xFFFFFFFFu, e, off);
            if (lane == 0) g_e[n] = e;
            wmax = fmaxf(wmax, e);
        }
        if (lane == 0) red[warp] = wmax;
        __syncthreads();
        if (tid == 0) {
            float m = red[0];
            for (int w = 1; w < 8; w++) m = fmaxf(m, red[w]);
            smax = m;
        }
        __syncthreads();
        float m = smax;
        float ps = 0.0f;
        for (int n = gs + tid; n < ge; n += 256) {
            float ex = expf(g_e[n] - m);
            g_e[n] = ex;
            ps += ex;
        }
#pragma unroll
        for (int off = 16; off; off >>= 1) ps += __shfl_xor_sync(0xFFFFFFFFu, ps, off);
        if (lane == 0) red[warp] = ps;
        __syncthreads();
        if (tid == 0) {
            float s = 0.0f;
            for (int w = 0; w < 8; w++) s += red[w];
            ssum = s;
        }
        __syncthreads();
        float inv = 1.0f / (ssum + 1e-16f);
        float rx = 0.0f, ry = 0.0f;
        for (int n = gs + warp; n < ge; n += 8) {
            float a = g_e[n] * inv;
            float2 hv = *(const float2*)&g_h2[n * H2 + lane * 2];
            rx = fmaf(a, hv.x, rx);
            ry = fmaf(a, hv.y, ry);
        }
        rbuf[warp * H2 + lane * 2]     = rx;
        rbuf[warp * H2 + lane * 2 + 1] = ry;
        __syncthreads();
        if (tid < H2) {
            float r = 0.0f;
            for (int w = 0; w < 8; w++) r += rbuf[w * H2 + tid];
            qs[H2 + tid] = r;
        }
        __syncthreads();
    }

    for (int r = warp; r < 32; r += 8) {
        const float* wr = &fc1W[r * 2 * H2];
        float p = wr[lane] * qs[lane] + wr[lane + 32] * qs[lane + 32]
                + wr[lane + 64] * qs[lane + 64] + wr[lane + 96] * qs[lane + 96];
#pragma unroll
        for (int off = 16; off; off >>= 1) p += __shfl_xor_sync(0xFFFFFFFFu, p, off);
        if (lane == 0) gb[r] = gelu_f(p + fc1b[r]);
    }
    __syncthreads();
    if (warp == 0) {
        float v = gb[lane] * fc2W[lane];
#pragma unroll
        for (int off = 16; off; off >>= 1) v += __shfl_xor_sync(0xFFFFFFFFu, v, off);
        if (lane == 0) z[g] = v + fc2b[0];
    }
}

// ---------------- host ----------------
extern "C" void kernel_launch(void* const* d_in, const int* in_sizes, int n_in,
                              void* d_out, int out_size) {
    const float* x     = (const float*)d_in[0];
    const int*   ei    = (const int*)d_in[1];
    const int*   batch = (const int*)d_in[2];
    const float* nfcW  = (const float*)d_in[3];
    const float* nfcb  = (const float*)d_in[4];
    const float* gc1W  = (const float*)d_in[5];
    const float* gc1b  = (const float*)d_in[6];
    const float* gc2W  = (const float*)d_in[7];
    const float* gc2b  = (const float*)d_in[8];
    const float* l0Wih = (const float*)d_in[9];
    const float* l0Whh = (const float*)d_in[10];
    const float* l0bih = (const float*)d_in[11];
    const float* l0bhh = (const float*)d_in[12];
    const float* l1Wih = (const float*)d_in[13];
    const float* l1Whh = (const float*)d_in[14];
    const float* l1bih = (const float*)d_in[15];
    const float* l1bhh = (const float*)d_in[16];
    const float* fc1W  = (const float*)d_in[17];
    const float* fc1b  = (const float*)d_in[18];
    const float* fc2W  = (const float*)d_in[19];
    const float* fc2b  = (const float*)d_in[20];

    float* out = (float*)d_out;
    float* out_h = (out_size >= NG + NN * H2) ? (out + NG) : nullptr;

    size_t sm_nfc   = (size_t)(NF * H1 + 32 * NF) * 4;    // 40 KB
    size_t sm_conv1 = (size_t)(H1 * H1 + 32 * H1) * 4;    // 80 KB
    size_t sm_conv2 = (size_t)(H1 * H2 + 32 * H1) * 4;    // 48 KB
    cudaFuncSetAttribute(k_nfc,   cudaFuncAttributeMaxDynamicSharedMemorySize, (int)sm_nfc);
    cudaFuncSetAttribute(k_conv1, cudaFuncAttributeMaxDynamicSharedMemorySize, (int)sm_conv1);
    cudaFuncSetAttribute(k_conv2, cudaFuncAttributeMaxDynamicSharedMemorySize, (int)sm_conv2);

    k_zero<<<256, 256>>>();
    k_count<<<(NE + 255) / 256, 256>>>(ei);
    k_scanA<<<NBLK, 256>>>();
    k_scanB<<<1, 128>>>();
    k_scanC<<<NBLK, 256>>>();
    k_scatter<<<(NE + 255) / 256, 256>>>(ei);
    k_gstart<<<(NN + 255) / 256, 256>>>(batch);
    k_nfc<<<NN / 32, 256, sm_nfc>>>(x, nfcW, nfcb);
    k_conv1<<<NN / 32, 256, sm_conv1>>>(gc1W, gc1b);
    k_conv2<<<NN / 32, 256, sm_conv2>>>(gc2W, gc2b, out_h);
    k_s2s<<<NG, 256>>>(l0Wih, l0Whh, l0bih, l0bhh,
                       l1Wih, l1Whh, l1bih, l1bhh,
                       fc1W, fc1b, fc2W, fc2b, out);
}

// round 7
// speedup vs baseline: 4.6887x; 1.1766x over previous
#include <cuda_runtime.h>
#include <math.h>

#define NN 100000
#define NE 1600000
#define NG 512
#define NF 64
#define H1 128
#define H2 64
#define SCB 98            // scan blocks: ceil(NN/1024)
#define TPB 64            // nodes per block in dense kernels

// ---------------- device scratch ----------------
__device__ float g_h1[NN * H1];
__device__ float g_s1[NN * H1];
__device__ float g_h2[NN * H2];
__device__ float g_e[NN];
__device__ int   g_cnt[NN];
__device__ int   g_off[NN + 1];
__device__ int   g_cur[NN];
__device__ int   g_csr[NE];
__device__ int   g_gs[NG + 1];
__device__ int   g_sagg[SCB];
__device__ int   g_sflag[SCB];

__device__ __forceinline__ float gelu_f(float x) {
    return 0.5f * x * (1.0f + erff(x * 0.70710678118654752f));
}
__device__ __forceinline__ float sigmoid_f(float x) {
    return 1.0f / (1.0f + expf(-x));
}

// ---------------- init ----------------
__global__ void __launch_bounds__(256) k_zero() {
    int i = blockIdx.x * blockDim.x + threadIdx.x;
    int T = gridDim.x * blockDim.x;
    for (int j = i; j < NN; j += T) { g_cnt[j] = 0; g_cur[j] = 0; }
    if (i < SCB) { g_sflag[i] = 0; g_sagg[i] = 0; }
    if (i == 0) g_off[NN] = NE;
}

// ---------------- nfc (64 nodes/block) + edge counting fold ----------------
__global__ void __launch_bounds__(256) k_nfc(const float* __restrict__ x,
                                             const float* __restrict__ W,
                                             const float* __restrict__ b,
                                             const int* __restrict__ ei) {
    extern __shared__ float sm[];
    float* wt = sm;                  // [64][128] transposed (32 KB)
    float* xs = sm + NF * H1;        // [64][64]  (16 KB)
    int tid = threadIdx.x;

    // edge counting: this block's slice of 1024 edges (overlaps with smem fill)
    {
        int eb = blockIdx.x * 1024 + tid * 4;
#pragma unroll
        for (int i = 0; i < 4; i++)
            if (eb + i < NE) atomicAdd(&g_cnt[ei[NE + eb + i]], 1);
    }

    for (int i = tid; i < H1 * NF; i += 256) {
        int o = i >> 6, k = i & 63;
        wt[k * H1 + o] = W[i];
    }
    int warp = tid >> 5, lane = tid & 31;
    int nb = blockIdx.x * TPB;
#pragma unroll
    for (int t = 0; t < 8; t++) {
        int row = warp * 8 + t;
        int n = nb + row;
        if (n < NN) {
            float2 xv = *(const float2*)&x[n * NF + lane * 2];
            *(float2*)&xs[row * NF + lane * 2] = xv;
        }
    }
    __syncthreads();
    float4 bias = *(const float4*)&b[lane * 4];
    float4 acc[8];
#pragma unroll
    for (int t = 0; t < 8; t++) acc[t] = bias;
    const float* rp = &xs[warp * 8 * NF];
#pragma unroll 4
    for (int k = 0; k < NF; k++) {
        float4 w = *(const float4*)&wt[k * H1 + lane * 4];
#pragma unroll
        for (int t = 0; t < 8; t++) {
            float v = rp[t * NF + k];
            acc[t].x = fmaf(v, w.x, acc[t].x);
            acc[t].y = fmaf(v, w.y, acc[t].y);
            acc[t].z = fmaf(v, w.z, acc[t].z);
            acc[t].w = fmaf(v, w.w, acc[t].w);
        }
    }
#pragma unroll
    for (int t = 0; t < 8; t++) {
        int n = nb + warp * 8 + t;
        if (n < NN) {
            float4 a = acc[t];
            a.x = gelu_f(a.x); a.y = gelu_f(a.y);
            a.z = gelu_f(a.z); a.w = gelu_f(a.w);
            *(float4*)&g_h1[n * H1 + lane * 4] = a;
        }
    }
}

// ---------------- single-pass scan (decoupled lookback) + gstart fold ----------------
__global__ void __launch_bounds__(256) k_scan(const int* __restrict__ batch) {
    __shared__ int sm[256];
    __shared__ int addsh;
    int tid = threadIdx.x;
    int b = blockIdx.x;
    if (tid == 0) addsh = 0;
    int idx = b * 1024 + tid * 4;
    int v0 = 0, v1 = 0, v2 = 0, v3 = 0;
    if (idx     < NN) v0 = g_cnt[idx];
    if (idx + 1 < NN) v1 = g_cnt[idx + 1];
    if (idx + 2 < NN) v2 = g_cnt[idx + 2];
    if (idx + 3 < NN) v3 = g_cnt[idx + 3];
    int t = v0 + v1 + v2 + v3;
    sm[tid] = t;
    __syncthreads();
    for (int off = 1; off < 256; off <<= 1) {
        int u = (tid >= off) ? sm[tid - off] : 0;
        __syncthreads();
        sm[tid] += u;
        __syncthreads();
    }
    // publish block aggregate
    if (tid == 0) {
        g_sagg[b] = sm[255];
        __threadfence();
        atomicExch(&g_sflag[b], 1);
    }
    int excl = sm[tid] - t;
    // lookback: sum aggregates of predecessor blocks
    int myadd = 0;
    for (int i = tid; i < b; i += 256) {
        while (((volatile int*)g_sflag)[i] == 0) { }
        myadd += ((volatile int*)g_sagg)[i];
    }
#pragma unroll
    for (int off = 16; off; off >>= 1) myadd += __shfl_xor_sync(0xFFFFFFFFu, myadd, off);
    if ((tid & 31) == 0 && myadd) atomicAdd(&addsh, myadd);
    __syncthreads();
    int add = addsh;
    if (idx     < NN) g_off[idx]     = excl + add;
    if (idx + 1 < NN) g_off[idx + 1] = excl + add + v0;
    if (idx + 2 < NN) g_off[idx + 2] = excl + add + v0 + v1;
    if (idx + 3 < NN) g_off[idx + 3] = excl + add + v0 + v1 + v2;
    // gstart fold
#pragma unroll
    for (int i = 0; i < 4; i++) {
        int n = idx + i;
        if (n < NN) {
            int bb = batch[n];
            int bp = (n == 0) ? -1 : batch[n - 1];
            for (int g = bp + 1; g <= bb; g++) g_gs[g] = n;
            if (n == NN - 1)
                for (int g = bb + 1; g <= NG; g++) g_gs[g] = NN;
        }
    }
}

__global__ void __launch_bounds__(256) k_scatter(const int* __restrict__ ei) {
    int e = blockIdx.x * blockDim.x + threadIdx.x;
    if (e < NE) {
        int s = ei[e];
        int d = ei[NE + e];
        int pos = atomicAdd(&g_cur[d], 1);
        g_csr[g_off[d] + pos] = s;
    }
}

// ---------------- conv1: gather+self, GEMM 128x128, gelu (64 nodes/block) ----------------
__global__ void __launch_bounds__(256) k_conv1(const float* __restrict__ W,
                                               const float* __restrict__ b) {
    extern __shared__ float sm[];
    float* wt  = sm;                 // [128][128] (64 KB)
    float* agg = sm + H1 * H1;       // [64][128] (32 KB)
    int tid = threadIdx.x;
    for (int i = tid; i < H1 * H1; i += 256) {
        int o = i >> 7, k = i & 127;
        wt[k * H1 + o] = W[i];
    }
    int warp = tid >> 5, lane = tid & 31;
    int nb = blockIdx.x * TPB;
    for (int t = 0; t < 8; t++) {
        int row = warp * 8 + t;
        int n = nb + row;
        if (n >= NN) break;
        float4 a = *(const float4*)&g_h1[n * H1 + lane * 4];
        int e0 = g_off[n], e1 = g_off[n + 1];
        int j = e0;
        for (; j + 3 < e1; j += 4) {
            int s0 = g_csr[j], s1 = g_csr[j + 1], s2 = g_csr[j + 2], s3 = g_csr[j + 3];
            float4 v0 = *(const float4*)&g_h1[s0 * H1 + lane * 4];
            float4 v1 = *(const float4*)&g_h1[s1 * H1 + lane * 4];
            float4 v2 = *(const float4*)&g_h1[s2 * H1 + lane * 4];
            float4 v3 = *(const float4*)&g_h1[s3 * H1 + lane * 4];
            a.x += (v0.x + v1.x) + (v2.x + v3.x);
            a.y += (v0.y + v1.y) + (v2.y + v3.y);
            a.z += (v0.z + v1.z) + (v2.z + v3.z);
            a.w += (v0.w + v1.w) + (v2.w + v3.w);
        }
        for (; j < e1; j++) {
            int s0 = g_csr[j];
            float4 v0 = *(const float4*)&g_h1[s0 * H1 + lane * 4];
            a.x += v0.x; a.y += v0.y; a.z += v0.z; a.w += v0.w;
        }
        *(float4*)&agg[row * H1 + lane * 4] = a;
    }
    __syncthreads();
    float4 bias = *(const float4*)&b[lane * 4];
    float4 acc[8];
#pragma unroll
    for (int t = 0; t < 8; t++) acc[t] = bias;
    const float* rp = &agg[warp * 8 * H1];
#pragma unroll 4
    for (int k = 0; k < H1; k++) {
        float4 w = *(const float4*)&wt[k * H1 + lane * 4];
#pragma unroll
        for (int t = 0; t < 8; t++) {
            float v = rp[t * H1 + k];
            acc[t].x = fmaf(v, w.x, acc[t].x);
            acc[t].y = fmaf(v, w.y, acc[t].y);
            acc[t].z = fmaf(v, w.z, acc[t].z);
            acc[t].w = fmaf(v, w.w, acc[t].w);
        }
    }
#pragma unroll
    for (int t = 0; t < 8; t++) {
        int n = nb + warp * 8 + t;
        if (n < NN) {
            float4 a = acc[t];
            a.x = gelu_f(a.x); a.y = gelu_f(a.y);
            a.z = gelu_f(a.z); a.w = gelu_f(a.w);
            *(float4*)&g_s1[n * H1 + lane * 4] = a;
        }
    }
}

// ---------------- conv2: gather+self, GEMM 128->64, gelu, normalize (64 nodes/block) ----------------
__global__ void __launch_bounds__(256) k_conv2(const float* __restrict__ W,
                                               const float* __restrict__ b,
                                               float* __restrict__ out_h) {
    extern __shared__ float sm[];
    float* wt  = sm;                 // [128][64] (32 KB)
    float* agg = sm + H1 * H2;       // [64][128] (32 KB)
    int tid = threadIdx.x;
    for (int i = tid; i < H2 * H1; i += 256) {
        int o = i >> 7, k = i & 127;
        wt[k * H2 + o] = W[i];
    }
    int warp = tid >> 5, lane = tid & 31;
    int nb = blockIdx.x * TPB;
    for (int t = 0; t < 8; t++) {
        int row = warp * 8 + t;
        int n = nb + row;
        if (n >= NN) break;
        float4 a = *(const float4*)&g_s1[n * H1 + lane * 4];
        int e0 = g_off[n], e1 = g_off[n + 1];
        int j = e0;
        for (; j + 3 < e1; j += 4) {
            int s0 = g_csr[j], s1 = g_csr[j + 1], s2 = g_csr[j + 2], s3 = g_csr[j + 3];
            float4 v0 = *(const float4*)&g_s1[s0 * H1 + lane * 4];
            float4 v1 = *(const float4*)&g_s1[s1 * H1 + lane * 4];
            float4 v2 = *(const float4*)&g_s1[s2 * H1 + lane * 4];
            float4 v3 = *(const float4*)&g_s1[s3 * H1 + lane * 4];
            a.x += (v0.x + v1.x) + (v2.x + v3.x);
            a.y += (v0.y + v1.y) + (v2.y + v3.y);
            a.z += (v0.z + v1.z) + (v2.z + v3.z);
            a.w += (v0.w + v1.w) + (v2.w + v3.w);
        }
        for (; j < e1; j++) {
            int s0 = g_csr[j];
            float4 v0 = *(const float4*)&g_s1[s0 * H1 + lane * 4];
            a.x += v0.x; a.y += v0.y; a.z += v0.z; a.w += v0.w;
        }
        *(float4*)&agg[row * H1 + lane * 4] = a;
    }
    __syncthreads();
    float2 bias = *(const float2*)&b[lane * 2];
    float2 acc[8];
#pragma unroll
    for (int t = 0; t < 8; t++) acc[t] = bias;
    const float* rp = &agg[warp * 8 * H1];
#pragma unroll 4
    for (int k = 0; k < H1; k++) {
        float2 w = *(const float2*)&wt[k * H2 + lane * 2];
#pragma unroll
        for (int t = 0; t < 8; t++) {
            float v = rp[t * H1 + k];
            acc[t].x = fmaf(v, w.x, acc[t].x);
            acc[t].y = fmaf(v, w.y, acc[t].y);
        }
    }
#pragma unroll
    for (int t = 0; t < 8; t++) {
        int n = nb + warp * 8 + t;
        if (n < NN) {
            float2 a = acc[t];
            a.x = gelu_f(a.x);
            a.y = gelu_f(a.y);
            float ssq = a.x * a.x + a.y * a.y;
#pragma unroll
            for (int off = 16; off; off >>= 1) ssq += __shfl_xor_sync(0xFFFFFFFFu, ssq, off);
            float inv = 1.0f / fmaxf(sqrtf(ssq), 1e-12f);
            a.x *= inv; a.y *= inv;
            *(float2*)&g_h2[n * H2 + lane * 2] = a;
            if (out_h) *(float2*)&out_h[n * H2 + lane * 2] = a;
        }
    }
}

// ---------------- fused Set2Set (4 steps) + final MLP: one block per graph ----------------
__global__ void __launch_bounds__(256) k_s2s(
        const float* __restrict__ Wih0, const float* __restrict__ Whh0,
        const float* __restrict__ bih0, const float* __restrict__ bhh0,
        const float* __restrict__ Wih1, const float* __restrict__ Whh1,
        const float* __restrict__ bih1, const float* __restrict__ bhh1,
        const float* __restrict__ fc1W, const float* __restrict__ fc1b,
        const float* __restrict__ fc2W, const float* __restrict__ fc2b,
        float* __restrict__ z) {
    __shared__ float h0[H2], c0[H2], h1[H2], c1[H2], qs[2 * H2];
    __shared__ float gb[4 * H2], red[8], rbuf[8 * H2];
    __shared__ float smax, ssum;
    int g = blockIdx.x;
    int tid = threadIdx.x, warp = tid >> 5, lane = tid & 31;
    int gs = g_gs[g], ge = g_gs[g + 1];
    if (tid < H2) { h0[tid] = 0.0f; c0[tid] = 0.0f; h1[tid] = 0.0f; c1[tid] = 0.0f; }
    if (tid < 2 * H2) qs[tid] = 0.0f;
    __syncthreads();

    for (int step = 0; step < 4; step++) {
        for (int r = warp; r < 4 * H2; r += 8) {
            const float* wi = &Wih0[r * 2 * H2];
            float p = wi[lane] * qs[lane] + wi[lane + 32] * qs[lane + 32]
                    + wi[lane + 64] * qs[lane + 64] + wi[lane + 96] * qs[lane + 96];
            const float* wh = &Whh0[r * H2];
            p += wh[lane] * h0[lane] + wh[lane + 32] * h0[lane + 32];
#pragma unroll
            for (int off = 16; off; off >>= 1) p += __shfl_xor_sync(0xFFFFFFFFu, p, off);
            if (lane == 0) gb[r] = p + bih0[r] + bhh0[r];
        }
        __syncthreads();
        if (tid < H2) {
            float i = sigmoid_f(gb[tid]);
            float f = sigmoid_f(gb[H2 + tid]);
            float gg = tanhf(gb[2 * H2 + tid]);
            float o = sigmoid_f(gb[3 * H2 + tid]);
            float c = f * c0[tid] + i * gg;
            c0[tid] = c;
            h0[tid] = o * tanhf(c);
        }
        __syncthreads();
        for (int r = warp; r < 4 * H2; r += 8) {
            const float* wi = &Wih1[r * H2];
            float p = wi[lane] * h0[lane] + wi[lane + 32] * h0[lane + 32];
            const float* wh = &Whh1[r * H2];
            p += wh[lane] * h1[lane] + wh[lane + 32] * h1[lane + 32];
#pragma unroll
            for (int off = 16; off; off >>= 1) p += __shfl_xor_sync(0xFFFFFFFFu, p, off);
            if (lane == 0) gb[r] = p + bih1[r] + bhh1[r];
        }
        __syncthreads();
        if (tid < H2) {
            float i = sigmoid_f(gb[tid]);
            float f = sigmoid_f(gb[H2 + tid]);
            float gg = tanhf(gb[2 * H2 + tid]);
            float o = sigmoid_f(gb[3 * H2 + tid]);
            float c = f * c1[tid] + i * gg;
            c1[tid] = c;
            float h = o * tanhf(c);
            h1[tid] = h;
            qs[tid] = h;
        }
        __syncthreads();
        float wmax = -3.4e38f;
        for (int n = gs + warp; n < ge; n += 8) {
            float2 hv = *(const float2*)&g_h2[n * H2 + lane * 2];
            float e = hv.x * qs[lane * 2] + hv.y * qs[lane * 2 + 1];
#pragma unroll
            for (int off = 16; off; off >>= 1) e += __shfl_xor_sync(0xFFFFFFFFu, e, off);
            if (lane == 0) g_e[n] = e;
            wmax = fmaxf(wmax, e);
        }
        if (lane == 0) red[warp] = wmax;
        __syncthreads();
        if (tid == 0) {
            float m = red[0];
            for (int w = 1; w < 8; w++) m = fmaxf(m, red[w]);
            smax = m;
        }
        __syncthreads();
        float m = smax;
        float ps = 0.0f;
        for (int n = gs + tid; n < ge; n += 256) {
            float ex = expf(g_e[n] - m);
            g_e[n] = ex;
            ps += ex;
        }
#pragma unroll
        for (int off = 16; off; off >>= 1) ps += __shfl_xor_sync(0xFFFFFFFFu, ps, off);
        if (lane == 0) red[warp] = ps;
        __syncthreads();
        if (tid == 0) {
            float s = 0.0f;
            for (int w = 0; w < 8; w++) s += red[w];
            ssum = s;
        }
        __syncthreads();
        float inv = 1.0f / (ssum + 1e-16f);
        float rx = 0.0f, ry = 0.0f;
        for (int n = gs + warp; n < ge; n += 8) {
            float a = g_e[n] * inv;
            float2 hv = *(const float2*)&g_h2[n * H2 + lane * 2];
            rx = fmaf(a, hv.x, rx);
            ry = fmaf(a, hv.y, ry);
        }
        rbuf[warp * H2 + lane * 2]     = rx;
        rbuf[warp * H2 + lane * 2 + 1] = ry;
        __syncthreads();
        if (tid < H2) {
            float r = 0.0f;
            for (int w = 0; w < 8; w++) r += rbuf[w * H2 + tid];
            qs[H2 + tid] = r;
        }
        __syncthreads();
    }

    for (int r = warp; r < 32; r += 8) {
        const float* wr = &fc1W[r * 2 * H2];
        float p = wr[lane] * qs[lane] + wr[lane + 32] * qs[lane + 32]
                + wr[lane + 64] * qs[lane + 64] + wr[lane + 96] * qs[lane + 96];
#pragma unroll
        for (int off = 16; off; off >>= 1) p += __shfl_xor_sync(0xFFFFFFFFu, p, off);
        if (lane == 0) gb[r] = gelu_f(p + fc1b[r]);
    }
    __syncthreads();
    if (warp == 0) {
        float v = gb[lane] * fc2W[lane];
#pragma unroll
        for (int off = 16; off; off >>= 1) v += __shfl_xor_sync(0xFFFFFFFFu, v, off);
        if (lane == 0) z[g] = v + fc2b[0];
    }
}

// ---------------- host ----------------
extern "C" void kernel_launch(void* const* d_in, const int* in_sizes, int n_in,
                              void* d_out, int out_size) {
    const float* x     = (const float*)d_in[0];
    const int*   ei    = (const int*)d_in[1];
    const int*   batch = (const int*)d_in[2];
    const float* nfcW  = (const float*)d_in[3];
    const float* nfcb  = (const float*)d_in[4];
    const float* gc1W  = (const float*)d_in[5];
    const float* gc1b  = (const float*)d_in[6];
    const float* gc2W  = (const float*)d_in[7];
    const float* gc2b  = (const float*)d_in[8];
    const float* l0Wih = (const float*)d_in[9];
    const float* l0Whh = (const float*)d_in[10];
    const float* l0bih = (const float*)d_in[11];
    const float* l0bhh = (const float*)d_in[12];
    const float* l1Wih = (const float*)d_in[13];
    const float* l1Whh = (const float*)d_in[14];
    const float* l1bih = (const float*)d_in[15];
    const float* l1bhh = (const float*)d_in[16];
    const float* fc1W  = (const float*)d_in[17];
    const float* fc1b  = (const float*)d_in[18];
    const float* fc2W  = (const float*)d_in[19];
    const float* fc2b  = (const float*)d_in[20];

    float* out = (float*)d_out;
    float* out_h = (out_size >= NG + NN * H2) ? (out + NG) : nullptr;

    int nblk = (NN + TPB - 1) / TPB;                      // 1563
    size_t sm_nfc   = (size_t)(NF * H1 + TPB * NF) * 4;   // 48 KB
    size_t sm_conv1 = (size_t)(H1 * H1 + TPB * H1) * 4;   // 96 KB
    size_t sm_conv2 = (size_t)(H1 * H2 + TPB * H1) * 4;   // 64 KB
    cudaFuncSetAttribute(k_nfc,   cudaFuncAttributeMaxDynamicSharedMemorySize, (int)sm_nfc);
    cudaFuncSetAttribute(k_conv1, cudaFuncAttributeMaxDynamicSharedMemorySize, (int)sm_conv1);
    cudaFuncSetAttribute(k_conv2, cudaFuncAttributeMaxDynamicSharedMemorySize, (int)sm_conv2);

    k_zero<<<128, 256>>>();
    k_nfc<<<nblk, 256, sm_nfc>>>(x, nfcW, nfcb, ei);
    k_scan<<<SCB, 256>>>(batch);
    k_scatter<<<(NE + 255) / 256, 256>>>(ei);
    k_conv1<<<nblk, 256, sm_conv1>>>(gc1W, gc1b);
    k_conv2<<<nblk, 256, sm_conv2>>>(gc2W, gc2b, out_h);
    k_s2s<<<NG, 256>>>(l0Wih, l0Whh, l0bih, l0bhh,
                       l1Wih, l1Whh, l1bih, l1bhh,
                       fc1W, fc1b, fc2W, fc2b, out);
}

// round 9
// speedup vs baseline: 4.9001x; 1.0451x over previous
#include <cuda_runtime.h>
#include <math.h>

#define NN 100000
#define NE 1600000
#define NG 512
#define NF 64
#define H1 128
#define H2 64
#define SCB 98            // scan blocks: ceil(NN/1024)
#define TPB 64            // nodes per block in dense kernels

// ---------------- device scratch ----------------
__device__ float g_h1[NN * H1];
__device__ float g_s1[NN * H1];
__device__ float g_h2[NN * H2];
__device__ float g_e[NN];
__device__ int   g_cnt[NN];
__device__ int   g_off[NN + 1];
__device__ int   g_cur[NN];
__device__ int   g_csr[NE];
__device__ int   g_gs[NG + 1];
__device__ int   g_sagg[SCB];
__device__ int   g_sflag[SCB];

__device__ __forceinline__ float gelu_f(float x) {
    return 0.5f * x * (1.0f + erff(x * 0.70710678118654752f));
}
__device__ __forceinline__ float sigmoid_f(float x) {
    return 1.0f / (1.0f + expf(-x));
}

// ---------------- init ----------------
__global__ void __launch_bounds__(256) k_zero() {
    int i = blockIdx.x * blockDim.x + threadIdx.x;
    int T = gridDim.x * blockDim.x;
    for (int j = i; j < NN; j += T) { g_cnt[j] = 0; g_cur[j] = 0; }
    if (i < SCB) { g_sflag[i] = 0; g_sagg[i] = 0; }
    if (i == 0) g_off[NN] = NE;
}

// ---------------- nfc (64 nodes/block) + edge counting fold ----------------
__global__ void __launch_bounds__(256) k_nfc(const float* __restrict__ x,
                                             const float* __restrict__ W,
                                             const float* __restrict__ b,
                                             const int* __restrict__ ei) {
    extern __shared__ float sm[];
    float* wt = sm;                  // [64][128] transposed (32 KB)
    float* xs = sm + NF * H1;        // [64][64]  (16 KB)
    int tid = threadIdx.x;

    // edge counting: this block's slice of 1024 edges
    {
        int eb = blockIdx.x * 1024 + tid * 4;
#pragma unroll
        for (int i = 0; i < 4; i++)
            if (eb + i < NE) atomicAdd(&g_cnt[ei[NE + eb + i]], 1);
    }

    for (int i = tid; i < H1 * NF; i += 256) {
        int o = i >> 6, k = i & 63;
        wt[k * H1 + o] = W[i];
    }
    int warp = tid >> 5, lane = tid & 31;
    int nb = blockIdx.x * TPB;
#pragma unroll
    for (int t = 0; t < 8; t++) {
        int row = warp * 8 + t;
        int n = nb + row;
        if (n < NN) {
            float2 xv = *(const float2*)&x[n * NF + lane * 2];
            *(float2*)&xs[row * NF + lane * 2] = xv;
        }
    }
    __syncthreads();
    float4 bias = *(const float4*)&b[lane * 4];
    float4 acc[8];
#pragma unroll
    for (int t = 0; t < 8; t++) acc[t] = bias;
    const float* rp = &xs[warp * 8 * NF];
#pragma unroll 4
    for (int k = 0; k < NF; k++) {
        float4 w = *(const float4*)&wt[k * H1 + lane * 4];
#pragma unroll
        for (int t = 0; t < 8; t++) {
            float v = rp[t * NF + k];
            acc[t].x = fmaf(v, w.x, acc[t].x);
            acc[t].y = fmaf(v, w.y, acc[t].y);
            acc[t].z = fmaf(v, w.z, acc[t].z);
            acc[t].w = fmaf(v, w.w, acc[t].w);
        }
    }
#pragma unroll
    for (int t = 0; t < 8; t++) {
        int n = nb + warp * 8 + t;
        if (n < NN) {
            float4 a = acc[t];
            a.x = gelu_f(a.x); a.y = gelu_f(a.y);
            a.z = gelu_f(a.z); a.w = gelu_f(a.w);
            *(float4*)&g_h1[n * H1 + lane * 4] = a;
        }
    }
}

// ---------------- single-pass scan (decoupled lookback) + gstart fold ----------------
__global__ void __launch_bounds__(256) k_scan(const int* __restrict__ batch) {
    __shared__ int sm[256];
    __shared__ int addsh;
    int tid = threadIdx.x;
    int b = blockIdx.x;
    if (tid == 0) addsh = 0;
    int idx = b * 1024 + tid * 4;
    int v0 = 0, v1 = 0, v2 = 0, v3 = 0;
    if (idx     < NN) v0 = g_cnt[idx];
    if (idx + 1 < NN) v1 = g_cnt[idx + 1];
    if (idx + 2 < NN) v2 = g_cnt[idx + 2];
    if (idx + 3 < NN) v3 = g_cnt[idx + 3];
    int t = v0 + v1 + v2 + v3;
    sm[tid] = t;
    __syncthreads();
    for (int off = 1; off < 256; off <<= 1) {
        int u = (tid >= off) ? sm[tid - off] : 0;
        __syncthreads();
        sm[tid] += u;
        __syncthreads();
    }
    if (tid == 0) {
        g_sagg[b] = sm[255];
        __threadfence();
        atomicExch(&g_sflag[b], 1);
    }
    int excl = sm[tid] - t;
    int myadd = 0;
    for (int i = tid; i < b; i += 256) {
        while (((volatile int*)g_sflag)[i] == 0) { }
        myadd += ((volatile int*)g_sagg)[i];
    }
#pragma unroll
    for (int off = 16; off; off >>= 1) myadd += __shfl_xor_sync(0xFFFFFFFFu, myadd, off);
    if ((tid & 31) == 0 && myadd) atomicAdd(&addsh, myadd);
    __syncthreads();
    int add = addsh;
    if (idx     < NN) g_off[idx]     = excl + add;
    if (idx + 1 < NN) g_off[idx + 1] = excl + add + v0;
    if (idx + 2 < NN) g_off[idx + 2] = excl + add + v0 + v1;
    if (idx + 3 < NN) g_off[idx + 3] = excl + add + v0 + v1 + v2;
#pragma unroll
    for (int i = 0; i < 4; i++) {
        int n = idx + i;
        if (n < NN) {
            int bb = batch[n];
            int bp = (n == 0) ? -1 : batch[n - 1];
            for (int g = bp + 1; g <= bb; g++) g_gs[g] = n;
            if (n == NN - 1)
                for (int g = bb + 1; g <= NG; g++) g_gs[g] = NN;
        }
    }
}

__global__ void __launch_bounds__(256) k_scatter(const int* __restrict__ ei) {
    int e = blockIdx.x * blockDim.x + threadIdx.x;
    if (e < NE) {
        int s = ei[e];
        int d = ei[NE + e];
        int pos = atomicAdd(&g_cur[d], 1);
        g_csr[g_off[d] + pos] = s;
    }
}

// ---------------- gather: warp per node, agg = self + sum(neighbors) ----------------
// g_h1 -> g_s1. No smem, high occupancy -> deep MLP hides L2 latency.
__global__ void __launch_bounds__(256) k_gather() {
    int n = (blockIdx.x * 256 + threadIdx.x) >> 5;
    int lane = threadIdx.x & 31;
    if (n >= NN) return;
    const float* src = g_h1;
    float4 a = *(const float4*)&src[n * H1 + lane * 4];   // self
    int e0 = g_off[n], e1 = g_off[n + 1];
    int j = e0;
    for (; j + 7 < e1; j += 8) {
        int s0 = g_csr[j],     s1 = g_csr[j + 1], s2 = g_csr[j + 2], s3 = g_csr[j + 3];
        int s4 = g_csr[j + 4], s5 = g_csr[j + 5], s6 = g_csr[j + 6], s7 = g_csr[j + 7];
        float4 v0 = *(const float4*)&src[s0 * H1 + lane * 4];
        float4 v1 = *(const float4*)&src[s1 * H1 + lane * 4];
        float4 v2 = *(const float4*)&src[s2 * H1 + lane * 4];
        float4 v3 = *(const float4*)&src[s3 * H1 + lane * 4];
        float4 v4 = *(const float4*)&src[s4 * H1 + lane * 4];
        float4 v5 = *(const float4*)&src[s5 * H1 + lane * 4];
        float4 v6 = *(const float4*)&src[s6 * H1 + lane * 4];
        float4 v7 = *(const float4*)&src[s7 * H1 + lane * 4];
        a.x += ((v0.x + v1.x) + (v2.x + v3.x)) + ((v4.x + v5.x) + (v6.x + v7.x));
        a.y += ((v0.y + v1.y) + (v2.y + v3.y)) + ((v4.y + v5.y) + (v6.y + v7.y));
        a.z += ((v0.z + v1.z) + (v2.z + v3.z)) + ((v4.z + v5.z) + (v6.z + v7.z));
        a.w += ((v0.w + v1.w) + (v2.w + v3.w)) + ((v4.w + v5.w) + (v6.w + v7.w));
    }
    if (j + 3 < e1) {
        int s0 = g_csr[j], s1 = g_csr[j + 1], s2 = g_csr[j + 2], s3 = g_csr[j + 3];
        float4 v0 = *(const float4*)&src[s0 * H1 + lane * 4];
        float4 v1 = *(const float4*)&src[s1 * H1 + lane * 4];
        float4 v2 = *(const float4*)&src[s2 * H1 + lane * 4];
        float4 v3 = *(const float4*)&src[s3 * H1 + lane * 4];
        a.x += (v0.x + v1.x) + (v2.x + v3.x);
        a.y += (v0.y + v1.y) + (v2.y + v3.y);
        a.z += (v0.z + v1.z) + (v2.z + v3.z);
        a.w += (v0.w + v1.w) + (v2.w + v3.w);
        j += 4;
    }
    for (; j < e1; j++) {
        int s0 = g_csr[j];
        float4 v0 = *(const float4*)&src[s0 * H1 + lane * 4];
        a.x += v0.x; a.y += v0.y; a.z += v0.z; a.w += v0.w;
    }
    *(float4*)&g_s1[n * H1 + lane * 4] = a;
}

// ---------------- gemm1: g_h1 = gelu(g_s1 @ W.T + b) ----------------
__global__ void __launch_bounds__(256) k_gemm1(const float* __restrict__ W,
                                               const float* __restrict__ b) {
    extern __shared__ float sm[];
    float* wt = sm;                  // [128][128] transposed (64 KB)
    float* as = sm + H1 * H1;        // [64][128] (32 KB)
    int tid = threadIdx.x;
    for (int i = tid; i < H1 * H1; i += 256) {
        int o = i >> 7, k = i & 127;
        wt[k * H1 + o] = W[i];
    }
    int nb = blockIdx.x * TPB;
    for (int i = tid; i < TPB * H1 / 4; i += 256) {
        int row = (i * 4) >> 7;
        int k   = (i * 4) & 127;
        int n = nb + row;
        float4 v = (n < NN) ? *(const float4*)&g_s1[n * H1 + k]
                            : make_float4(0.f, 0.f, 0.f, 0.f);
        *(float4*)&as[row * H1 + k] = v;
    }
    __syncthreads();
    int warp = tid >> 5, lane = tid & 31;
    float4 bias = *(const float4*)&b[lane * 4];
    float4 acc[8];
#pragma unroll
    for (int t = 0; t < 8; t++) acc[t] = bias;
    const float* rp = &as[warp * 8 * H1];
#pragma unroll 4
    for (int k = 0; k < H1; k++) {
        float4 w = *(const float4*)&wt[k * H1 + lane * 4];
#pragma unroll
        for (int t = 0; t < 8; t++) {
            float v = rp[t * H1 + k];
            acc[t].x = fmaf(v, w.x, acc[t].x);
            acc[t].y = fmaf(v, w.y, acc[t].y);
            acc[t].z = fmaf(v, w.z, acc[t].z);
            acc[t].w = fmaf(v, w.w, acc[t].w);
        }
    }
#pragma unroll
    for (int t = 0; t < 8; t++) {
        int n = nb + warp * 8 + t;
        if (n < NN) {
            float4 a = acc[t];
            a.x = gelu_f(a.x); a.y = gelu_f(a.y);
            a.z = gelu_f(a.z); a.w = gelu_f(a.w);
            *(float4*)&g_h1[n * H1 + lane * 4] = a;
        }
    }
}

// ---------------- gemm2: g_h2 = normalize(gelu(g_s1 @ W.T + b)) ----------------
__global__ void __launch_bounds__(256) k_gemm2(const float* __restrict__ W,
                                               const float* __restrict__ b,
                                               float* __restrict__ out_h) {
    extern __shared__ float sm[];
    float* wt = sm;                  // [128][64] transposed (32 KB)
    float* as = sm + H1 * H2;        // [64][128] (32 KB)
    int tid = threadIdx.x;
    for (int i = tid; i < H2 * H1; i += 256) {
        int o = i >> 7, k = i & 127;
        wt[k * H2 + o] = W[i];
    }
    int nb = blockIdx.x * TPB;
    for (int i = tid; i < TPB * H1 / 4; i += 256) {
        int row = (i * 4) >> 7;
        int k   = (i * 4) & 127;
        int n = nb + row;
        float4 v = (n < NN) ? *(const float4*)&g_s1[n * H1 + k]
                            : make_float4(0.f, 0.f, 0.f, 0.f);
        *(float4*)&as[row * H1 + k] = v;
    }
    __syncthreads();
    int warp = tid >> 5, lane = tid & 31;
    float2 bias = *(const float2*)&b[lane * 2];
    float2 acc[8];
#pragma unroll
    for (int t = 0; t < 8; t++) acc[t] = bias;
    const float* rp = &as[warp * 8 * H1];
#pragma unroll 4
    for (int k = 0; k < H1; k++) {
        float2 w = *(const float2*)&wt[k * H2 + lane * 2];
#pragma unroll
        for (int t = 0; t < 8; t++) {
            float v = rp[t * H1 + k];
            acc[t].x = fmaf(v, w.x, acc[t].x);
            acc[t].y = fmaf(v, w.y, acc[t].y);
        }
    }
#pragma unroll
    for (int t = 0; t < 8; t++) {
        int n = nb + warp * 8 + t;
        if (n < NN) {
            float2 a = acc[t];
            a.x = gelu_f(a.x);
            a.y = gelu_f(a.y);
            float ssq = a.x * a.x + a.y * a.y;
#pragma unroll
            for (int off = 16; off; off >>= 1) ssq += __shfl_xor_sync(0xFFFFFFFFu, ssq, off);
            float inv = 1.0f / fmaxf(sqrtf(ssq), 1e-12f);
            a.x *= inv; a.y *= inv;
            *(float2*)&g_h2[n * H2 + lane * 2] = a;
            if (out_h) *(float2*)&out_h[n * H2 + lane * 2] = a;
        }
    }
}

// ---------------- fused Set2Set (4 steps) + final MLP: one block per graph ----------------
__global__ void __launch_bounds__(256) k_s2s(
        const float* __restrict__ Wih0, const float* __restrict__ Whh0,
        const float* __restrict__ bih0, const float* __restrict__ bhh0,
        const float* __restrict__ Wih1, const float* __restrict__ Whh1,
        const float* __restrict__ bih1, const float* __restrict__ bhh1,
        const float* __restrict__ fc1W, const float* __restrict__ fc1b,
        const float* __restrict__ fc2W, const float* __restrict__ fc2b,
        float* __restrict__ z) {
    __shared__ float h0[H2], c0[H2], h1[H2], c1[H2], qs[2 * H2];
    __shared__ float gb[4 * H2], red[8], rbuf[8 * H2];
    __shared__ float smax, ssum;
    int g = blockIdx.x;
    int tid = threadIdx.x, warp = tid >> 5, lane = tid & 31;
    int gs = g_gs[g], ge = g_gs[g + 1];
    if (tid < H2) { h0[tid] = 0.0f; c0[tid] = 0.0f; h1[tid] = 0.0f; c1[tid] = 0.0f; }
    if (tid < 2 * H2) qs[tid] = 0.0f;
    __syncthreads();

    for (int step = 0; step < 4; step++) {
        for (int r = warp; r < 4 * H2; r += 8) {
            const float* wi = &Wih0[r * 2 * H2];
            float p = wi[lane] * qs[lane] + wi[lane + 32] * qs[lane + 32]
                    + wi[lane + 64] * qs[lane + 64] + wi[lane + 96] * qs[lane + 96];
            const float* wh = &Whh0[r * H2];
            p += wh[lane] * h0[lane] + wh[lane + 32] * h0[lane + 32];
#pragma unroll
            for (int off = 16; off; off >>= 1) p += __shfl_xor_sync(0xFFFFFFFFu, p, off);
            if (lane == 0) gb[r] = p + bih0[r] + bhh0[r];
        }
        __syncthreads();
        if (tid < H2) {
            float i = sigmoid_f(gb[tid]);
            float f = sigmoid_f(gb[H2 + tid]);
            float gg = tanhf(gb[2 * H2 + tid]);
            float o = sigmoid_f(gb[3 * H2 + tid]);
            float c = f * c0[tid] + i * gg;
            c0[tid] = c;
            h0[tid] = o * tanhf(c);
        }
        __syncthreads();
        for (int r = warp; r < 4 * H2; r += 8) {
            const float* wi = &Wih1[r * H2];
            float p = wi[lane] * h0[lane] + wi[lane + 32] * h0[lane + 32];
            const float* wh = &Whh1[r * H2];
            p += wh[lane] * h1[lane] + wh[lane + 32] * h1[lane + 32];
#pragma unroll
            for (int off = 16; off; off >>= 1) p += __shfl_xor_sync(0xFFFFFFFFu, p, off);
            if (lane == 0) gb[r] = p + bih1[r] + bhh1[r];
        }
        __syncthreads();
        if (tid < H2) {
            float i = sigmoid_f(gb[tid]);
            float f = sigmoid_f(gb[H2 + tid]);
            float gg = tanhf(gb[2 * H2 + tid]);
            float o = sigmoid_f(gb[3 * H2 + tid]);
            float c = f * c1[tid] + i * gg;
            c1[tid] = c;
            float h = o * tanhf(c);
            h1[tid] = h;
            qs[tid] = h;
        }
        __syncthreads();
        float wmax = -3.4e38f;
        for (int n = gs + warp; n < ge; n += 8) {
            float2 hv = *(const float2*)&g_h2[n * H2 + lane * 2];
            float e = hv.x * qs[lane * 2] + hv.y * qs[lane * 2 + 1];
#pragma unroll
            for (int off = 16; off; off >>= 1) e += __shfl_xor_sync(0xFFFFFFFFu, e, off);
            if (lane == 0) g_e[n] = e;
            wmax = fmaxf(wmax, e);
        }
        if (lane == 0) red[warp] = wmax;
        __syncthreads();
        if (tid == 0) {
            float m = red[0];
            for (int w = 1; w < 8; w++) m = fmaxf(m, red[w]);
            smax = m;
        }
        __syncthreads();
        float m = smax;
        float ps = 0.0f;
        for (int n = gs + tid; n < ge; n += 256) {
            float ex = expf(g_e[n] - m);
            g_e[n] = ex;
            ps += ex;
        }
#pragma unroll
        for (int off = 16; off; off >>= 1) ps += __shfl_xor_sync(0xFFFFFFFFu, ps, off);
        if (lane == 0) red[warp] = ps;
        __syncthreads();
        if (tid == 0) {
            float s = 0.0f;
            for (int w = 0; w < 8; w++) s += red[w];
            ssum = s;
        }
        __syncthreads();
        float inv = 1.0f / (ssum + 1e-16f);
        float rx = 0.0f, ry = 0.0f;
        for (int n = gs + warp; n < ge; n += 8) {
            float a = g_e[n] * inv;
            float2 hv = *(const float2*)&g_h2[n * H2 + lane * 2];
            rx = fmaf(a, hv.x, rx);
            ry = fmaf(a, hv.y, ry);
        }
        rbuf[warp * H2 + lane * 2]     = rx;
        rbuf[warp * H2 + lane * 2 + 1] = ry;
        __syncthreads();
        if (tid < H2) {
            float r = 0.0f;
            for (int w = 0; w < 8; w++) r += rbuf[w * H2 + tid];
            qs[H2 + tid] = r;
        }
        __syncthreads();
    }

    for (int r = warp; r < 32; r += 8) {
        const float* wr = &fc1W[r * 2 * H2];
        float p = wr[lane] * qs[lane] + wr[lane + 32] * qs[lane + 32]
                + wr[lane + 64] * qs[lane + 64] + wr[lane + 96] * qs[lane + 96];
#pragma unroll
        for (int off = 16; off; off >>= 1) p += __shfl_xor_sync(0xFFFFFFFFu, p, off);
        if (lane == 0) gb[r] = gelu_f(p + fc1b[r]);
    }
    __syncthreads();
    if (warp == 0) {
        float v = gb[lane] * fc2W[lane];
#pragma unroll
        for (int off = 16; off; off >>= 1) v += __shfl_xor_sync(0xFFFFFFFFu, v, off);
        if (lane == 0) z[g] = v + fc2b[0];
    }
}

// ---------------- host ----------------
extern "C" void kernel_launch(void* const* d_in, const int* in_sizes, int n_in,
                              void* d_out, int out_size) {
    const float* x     = (const float*)d_in[0];
    const int*   ei    = (const int*)d_in[1];
    const int*   batch = (const int*)d_in[2];
    const float* nfcW  = (const float*)d_in[3];
    const float* nfcb  = (const float*)d_in[4];
    const float* gc1W  = (const float*)d_in[5];
    const float* gc1b  = (const float*)d_in[6];
    const float* gc2W  = (const float*)d_in[7];
    const float* gc2b  = (const float*)d_in[8];
    const float* l0Wih = (const float*)d_in[9];
    const float* l0Whh = (const float*)d_in[10];
    const float* l0bih = (const float*)d_in[11];
    const float* l0bhh = (const float*)d_in[12];
    const float* l1Wih = (const float*)d_in[13];
    const float* l1Whh = (const float*)d_in[14];
    const float* l1bih = (const float*)d_in[15];
    const float* l1bhh = (const float*)d_in[16];
    const float* fc1W  = (const float*)d_in[17];
    const float* fc1b  = (const float*)d_in[18];
    const float* fc2W  = (const float*)d_in[19];
    const float* fc2b  = (const float*)d_in[20];

    float* out = (float*)d_out;
    float* out_h = (out_size >= NG + NN * H2) ? (out + NG) : nullptr;

    int nblk = (NN + TPB - 1) / TPB;                      // 1563
    int gblk = (NN * 32 + 255) / 256;                     // warp per node: 12500
    size_t sm_nfc   = (size_t)(NF * H1 + TPB * NF) * 4;   // 48 KB
    size_t sm_gemm1 = (size_t)(H1 * H1 + TPB * H1) * 4;   // 96 KB
    size_t sm_gemm2 = (size_t)(H1 * H2 + TPB * H1) * 4;   // 64 KB
    cudaFuncSetAttribute(k_nfc,   cudaFuncAttributeMaxDynamicSharedMemorySize, (int)sm_nfc);
    cudaFuncSetAttribute(k_gemm1, cudaFuncAttributeMaxDynamicSharedMemorySize, (int)sm_gemm1);
    cudaFuncSetAttribute(k_gemm2, cudaFuncAttributeMaxDynamicSharedMemorySize, (int)sm_gemm2);

    k_zero<<<128, 256>>>();
    k_nfc<<<nblk, 256, sm_nfc>>>(x, nfcW, nfcb, ei);
    k_scan<<<SCB, 256>>>(batch);
    k_scatter<<<(NE + 255) / 256, 256>>>(ei);
    // conv1: gather (g_h1 -> g_s1), gemm (g_s1 -> g_h1)
    k_gather<<<gblk, 256>>>();
    k_gemm1<<<nblk, 256, sm_gemm1>>>(gc1W, gc1b);
    // conv2: gather (g_h1 -> g_s1), gemm (g_s1 -> g_h2)
    k_gather<<<gblk, 256>>>();
    k_gemm2<<<nblk, 256, sm_gemm2>>>(gc2W, gc2b, out_h);
    k_s2s<<<NG, 256>>>(l0Wih, l0Whh, l0bih, l0bhh,
                       l1Wih, l1Whh, l1bih, l1bhh,
                       fc1W, fc1b, fc2W, fc2b, out);
}